// round 11
// baseline (speedup 1.0000x reference)
#include <cuda_runtime.h>
#include <cuda_fp16.h>
#include <math.h>
#include <stdint.h>

// Problem constants
#define BATCH 8
#define CIN   256
#define CH    256
#define HH    128
#define WW    128
#define HW    (HH*WW)          // 16384
#define NPIX  (BATCH*HW)       // 131072
#define NGRP  8
#define CPG   32

// Output layout (float32, tuple order, flattened+concatenated)
#define O_DMG   0
#define O_CORN  131072
#define O_PIX   393216
#define O_PRED  917504
#define O_MEAN  1048576
#define O_TOPK  1048608
#define O_AGG   1048640
#define O_AGGL  1048672

// -------- scratch (no cudaMalloc allowed) --------
__device__ float g_hd[(size_t)BATCH*CH*HW];          // damage conv3x3 out
__device__ float g_hs[(size_t)BATCH*CH*HW];          // severity conv3x3 out
// Weights, fp16 frag-permuted: [head][rs(9)][mg(16)][kk(16)][lane(32)] uint4
__device__ uint4 g_wah[2*9*16*16*32];
__device__ uint4 g_wal[2*9*16*16*32];
// Input, fp16 frag-permuted + pgp pair-packed, 3 x-shift planes:
// [s][n][pgp(1024)][kk(16)][lane(32)] uint4 = {b(pg even), b(pg odd)}
__device__ uint4 g_bah[(size_t)3*BATCH*1024*16*32];
__device__ uint4 g_bal[(size_t)3*BATCH*1024*16*32];
__device__ float g_part[2048*2];
__device__ float g_stats[2*BATCH*NGRP*2];
__device__ float g_mean_raw[BATCH*4];
__device__ float g_topk_raw[BATCH*4];
__device__ int   g_cnt[BATCH];

#define MMA_FP16(c, a, b0, b1) \
    asm volatile("mma.sync.aligned.m16n8k16.row.col.f32.f16.f16.f32 " \
        "{%0,%1,%2,%3},{%4,%5,%6,%7},{%8,%9},{%0,%1,%2,%3};" \
        : "+f"((c)[0]), "+f"((c)[1]), "+f"((c)[2]), "+f"((c)[3]) \
        : "r"((a).x), "r"((a).y), "r"((a).z), "r"((a).w), "r"(b0), "r"(b1))

#define CP_ASYNC16(dst, src) \
    asm volatile("cp.async.cg.shared.global [%0], [%1], 16;" :: "r"(dst), "l"(src) : "memory")
#define CP_ASYNC16P(dst, src, sz) \
    asm volatile("cp.async.cg.shared.global [%0], [%1], 16, %2;" :: "r"(dst), "l"(src), "r"(sz) : "memory")
#define CP_COMMIT()  asm volatile("cp.async.commit_group;" ::: "memory")
#define CP_WAIT1()   asm volatile("cp.async.wait_group 1;" ::: "memory")

__device__ __forceinline__ uint32_t pack_h2(float a, float b) {
    __half2 h = __halves2half2(__float2half_rn(a), __float2half_rn(b));
    return *reinterpret_cast<uint32_t*>(&h);
}

// ============================================================
// Kernel 0a: weight split into fp16 hi/lo, m16n8k16 frag-permuted.
// grid = (32, 9, 2), 256 thr.
// ============================================================
__global__ __launch_bounds__(256) void convert_w_kernel(
    const float* __restrict__ dw1, const float* __restrict__ sw1)
{
    const int i = blockIdx.x * 256 + threadIdx.x;    // 0..8191
    const int mg = i >> 9;
    const int kk = (i >> 5) & 15;
    const int l  = i & 31;
    const int g = l >> 2, tig = l & 3;
    const int head = blockIdx.z, rs = blockIdx.y;
    const int r = rs / 3, s = rs - r * 3;
    const float* w = head ? sw1 : dw1;

    const int co0 = mg * 16 + g;
    const int ciA = kk * 16 + 2 * tig;
    const int ciB = ciA + 8;

    float v[8];
    const int cos[8]  = {co0, co0, co0 + 8, co0 + 8, co0, co0, co0 + 8, co0 + 8};
    const int cis[8]  = {ciA, ciA + 1, ciA, ciA + 1, ciB, ciB + 1, ciB, ciB + 1};
#pragma unroll
    for (int q = 0; q < 8; q++)
        v[q] = w[((cos[q] * CIN + cis[q]) * 3 + r) * 3 + s];

    float h[8], lo[8];
#pragma unroll
    for (int q = 0; q < 8; q++) {
        h[q]  = __half2float(__float2half_rn(v[q]));
        lo[q] = v[q] - h[q];
    }
    uint4 hi4, lo4;
    hi4.x = pack_h2(h[0], h[1]);  lo4.x = pack_h2(lo[0], lo[1]);
    hi4.y = pack_h2(h[2], h[3]);  lo4.y = pack_h2(lo[2], lo[3]);
    hi4.z = pack_h2(h[4], h[5]);  lo4.z = pack_h2(lo[4], lo[5]);
    hi4.w = pack_h2(h[6], h[7]);  lo4.w = pack_h2(lo[6], lo[7]);
    const size_t off = (((size_t)(head * 9 + rs) * 16 + mg) * 16 + kk) * 32 + l;
    g_wah[off] = hi4;
    g_wal[off] = lo4;
}

// ============================================================
// Kernel 0b: input -> fp16 hi/lo frags via smem tile (coalesced).
// Block = (ci-half 128, one y-row). grid = (2, 128, 8), 256 thr.
// TP must be a multiple of 4 so the float4 row writes stay 16B-aligned.
// ============================================================
#define TP 132   // smem tile pitch (multiple of 4 -> float4-aligned rows)
__global__ __launch_bounds__(256) void convert_in_kernel(const float* __restrict__ in)
{
    extern __shared__ float tile[];   // [128][TP]
    const int cihalf = blockIdx.x, y = blockIdx.y, n = blockIdx.z;
    const int ci0 = cihalf * 128;
    const int tid = threadIdx.x;

    // load 128 ci x 128 x, coalesced
    {
        const int c = tid >> 1, xs = (tid & 1) * 64;
        const float* src = in + ((size_t)(n * CIN + ci0 + c)) * HW + y * WW + xs;
        float* drow = tile + c * TP + xs;
        const float4* s4 = (const float4*)src;
#pragma unroll
        for (int j = 0; j < 16; j++)
            *(float4*)(drow + j * 4) = s4[j];
    }
    __syncthreads();

    const int kk_rel = tid >> 5;      // 0..7
    const int l = tid & 31;
    const int g = l >> 2, tig = l & 3;
    const int kk = cihalf * 8 + kk_rel;
    const int cb = kk_rel * 16 + 2 * tig;

#pragma unroll
    for (int pgp_rel = 0; pgp_rel < 8; pgp_rel++) {
        const int pgp = y * 8 + pgp_rel;
#pragma unroll
        for (int s = 0; s < 3; s++) {
            uint4 hi4, lo4;
            uint32_t* hp = &hi4.x;
            uint32_t* lp = &lo4.x;
#pragma unroll
            for (int pr = 0; pr < 2; pr++) {
                const int x = (pgp_rel * 2 + pr) * 8 + g;
                const int xp = x + s - 1;
                const bool ok = ((unsigned)xp < (unsigned)WW);
                float v0 = ok ? tile[cb * TP + xp]       : 0.f;
                float v1 = ok ? tile[(cb + 1) * TP + xp] : 0.f;
                float v2 = ok ? tile[(cb + 8) * TP + xp] : 0.f;
                float v3 = ok ? tile[(cb + 9) * TP + xp] : 0.f;
                float h0 = __half2float(__float2half_rn(v0));
                float h1 = __half2float(__float2half_rn(v1));
                float h2 = __half2float(__float2half_rn(v2));
                float h3 = __half2float(__float2half_rn(v3));
                hp[pr * 2]     = pack_h2(h0, h1);
                hp[pr * 2 + 1] = pack_h2(h2, h3);
                lp[pr * 2]     = pack_h2(v0 - h0, v1 - h1);
                lp[pr * 2 + 1] = pack_h2(v2 - h2, v3 - h3);
            }
            const size_t off = (((size_t)(s * BATCH + n) * 1024 + pgp) * 16 + kk) * 32 + l;
            g_bah[off] = hi4;
            g_bal[off] = lo4;
        }
    }
}

// ============================================================
// Kernel 1: conv3x3 via 3-term fp16-split m16n8k16 implicit GEMM.
// CTA = 128co x 256px, 16 warps (4m x 4n) of 32x64. 512 threads.
// 36 stages (9 rs x 4), K=64/stage, 2-stage cp.async, 96KB/stage.
// grid = dim3(4, 512); blockIdx.x = head*2+cotile (B-sharing adjacent).
// ============================================================
#define STAGE_BYTES 98304   // Ah 16K | Al 16K | Bh 32K | Bl 32K
#define A_LO_OFF 16384
#define B_HI_OFF 32768
#define B_LO_OFF 65536

__device__ __forceinline__ void stage_load(
    char* sp, int st, int head, int cotile, int sn_base, int pgp0, int tid)
{
    const int rs  = st >> 2;
    const int kk0 = (st & 3) * 4;
    const int r = rs / 3, s = rs - r * 3;

    // A: 2048 uint4 (hi 1024 + lo 1024), 4 per thread
    const size_t abase = (((size_t)(head * 9 + rs) * 16 + cotile * 8) * 16 + kk0) * 32;
#pragma unroll
    for (int it = 0; it < 4; it++) {
        const int cid = tid + it * 512;
        const int prec = cid >> 10, cc = cid & 1023;
        const int mgl = cc >> 7, kkl = (cc >> 5) & 3, ll = cc & 31;
        const uint4* src = (prec ? g_wal : g_wah) + abase + mgl * 512 + kkl * 32 + ll;
        uint32_t dst = (uint32_t)__cvta_generic_to_shared(
            sp + prec * A_LO_OFF + ((mgl * 4 + kkl) * 32 + ll) * 16);
        CP_ASYNC16(dst, src);
    }
    // B: 4096 uint4 (hi+lo), 8 per thread; pgp row-shift predicate
    const size_t bbase = ((size_t)(s * BATCH + sn_base)) * 1024;
    const int pgpsh = pgp0 + (r - 1) * 8;
#pragma unroll
    for (int it = 0; it < 8; it++) {
        const int cid = tid + it * 512;
        const int prec = cid >> 11, cc = cid & 2047;
        const int kkl = cc >> 9, pgl = (cc >> 5) & 15, ll = cc & 31;
        const int pgpsrc = pgpsh + pgl;
        const unsigned ok = ((unsigned)pgpsrc < 1024u);
        const int pgpc = ok ? pgpsrc : 0;
        const uint4* src = (prec ? g_bal : g_bah)
            + ((bbase + pgpc) * 16 + kk0 + kkl) * 32 + ll;
        uint32_t dst = (uint32_t)__cvta_generic_to_shared(
            sp + B_HI_OFF + prec * 32768 + ((kkl * 16 + pgl) * 32 + ll) * 16);
        CP_ASYNC16P(dst, src, ok ? 16u : 0u);
    }
}

__global__ __launch_bounds__(512, 1) void conv_fp16_kernel()
{
    extern __shared__ char smem[];
    const int tid = threadIdx.x;
    const int lane = tid & 31;
    const int wid = tid >> 5;
    const int warp_m = wid & 3;        // 0..3 -> 32 co
    const int warp_n = wid >> 2;       // 0..3 -> 64 px
    const int g = lane >> 2, tig = lane & 3;

    const int head   = blockIdx.x >> 1;
    const int cotile = blockIdx.x & 1;
    const int ptile  = blockIdx.y;     // 0..511
    const int n      = ptile >> 6;
    const int pix0   = (ptile & 63) * 256;
    const int pgp0   = (ptile & 63) * 16;

    float c[2][8][4];
#pragma unroll
    for (int m = 0; m < 2; m++)
#pragma unroll
        for (int nn = 0; nn < 8; nn++)
#pragma unroll
            for (int q = 0; q < 4; q++) c[m][nn][q] = 0.f;

    char* buf0 = smem;
    char* buf1 = smem + STAGE_BYTES;

    stage_load(buf0, 0, head, cotile, n, pgp0, tid); CP_COMMIT();
    stage_load(buf1, 1, head, cotile, n, pgp0, tid); CP_COMMIT();

    for (int st = 0; st < 36; st++) {
        CP_WAIT1();
        __syncthreads();
        char* sp = (st & 1) ? buf1 : buf0;

#pragma unroll
        for (int kkl = 0; kkl < 4; kkl++) {
            uint4 Ah[2], Al[2];
#pragma unroll
            for (int m = 0; m < 2; m++) {
                const int mgl = warp_m * 2 + m;
                Ah[m] = *(const uint4*)(sp + ((mgl * 4 + kkl) * 32 + lane) * 16);
                Al[m] = *(const uint4*)(sp + A_LO_OFF + ((mgl * 4 + kkl) * 32 + lane) * 16);
            }
#pragma unroll
            for (int np = 0; np < 4; np++) {
                const int pgl = warp_n * 4 + np;
                uint4 bh = *(const uint4*)(sp + B_HI_OFF + ((kkl * 16 + pgl) * 32 + lane) * 16);
                uint4 bl = *(const uint4*)(sp + B_LO_OFF + ((kkl * 16 + pgl) * 32 + lane) * 16);
#pragma unroll
                for (int m = 0; m < 2; m++) {
                    MMA_FP16(c[m][np * 2],     Ah[m], bh.x, bh.y);
                    MMA_FP16(c[m][np * 2],     Al[m], bh.x, bh.y);
                    MMA_FP16(c[m][np * 2],     Ah[m], bl.x, bl.y);
                    MMA_FP16(c[m][np * 2 + 1], Ah[m], bh.z, bh.w);
                    MMA_FP16(c[m][np * 2 + 1], Al[m], bh.z, bh.w);
                    MMA_FP16(c[m][np * 2 + 1], Ah[m], bl.z, bl.w);
                }
            }
        }
        __syncthreads();
        if (st + 2 < 36)
            stage_load((st & 1) ? buf1 : buf0, st + 2, head, cotile, n, pgp0, tid);
        CP_COMMIT();
    }

    // store to g_hd / g_hs [n][co][pix]
    float* outb = head ? g_hs : g_hd;
#pragma unroll
    for (int m = 0; m < 2; m++) {
        const int co = cotile * 128 + (warp_m * 2 + m) * 16 + g;
        float* orow = outb + ((size_t)(n * CH + co)) * HW;
#pragma unroll
        for (int n8 = 0; n8 < 8; n8++) {
            const int pixl = pix0 + warp_n * 64 + n8 * 8 + tig * 2;
            *(float2*)(orow + pixl)                  = make_float2(c[m][n8][0], c[m][n8][1]);
            *(float2*)(orow + (size_t)8 * HW + pixl) = make_float2(c[m][n8][2], c[m][n8][3]);
        }
    }
}

// ============================================================
// Kernel 2a/2b: GroupNorm stats, two-phase.
// ============================================================
__global__ __launch_bounds__(256) void gn_partA_kernel()
{
    const int id = blockIdx.x;               // ((head*8+b)*8+g)*16+slice
    const int head = id >> 10;
    const int b = (id >> 7) & 7;
    const int g = (id >> 4) & 7;
    const int sl = id & 15;
    const float4* p4 = (const float4*)((head ? g_hs : g_hd)
                     + ((size_t)(b * CH + g * CPG)) * HW + sl * 32768);
    const int tid = threadIdx.x;
    float s = 0.f, s2 = 0.f;
    for (int i = tid; i < 8192; i += 256) {
        float4 v = p4[i];
        s += (v.x + v.y) + (v.z + v.w);
        s2 = fmaf(v.x, v.x, fmaf(v.y, v.y, fmaf(v.z, v.z, fmaf(v.w, v.w, s2))));
    }
    __shared__ float sh[256], sh2[256];
    sh[tid] = s; sh2[tid] = s2;
    __syncthreads();
    for (int off = 128; off > 0; off >>= 1) {
        if (tid < off) { sh[tid] += sh[tid + off]; sh2[tid] += sh2[tid + off]; }
        __syncthreads();
    }
    if (tid == 0) { g_part[id * 2] = sh[0]; g_part[id * 2 + 1] = sh2[0]; }
}

__global__ void gn_partB_kernel()
{
    const int t = threadIdx.x;
    if (t >= 128) return;
    float s = 0.f, s2 = 0.f;
    for (int i = 0; i < 16; i++) {
        s  += g_part[(t * 16 + i) * 2];
        s2 += g_part[(t * 16 + i) * 2 + 1];
    }
    const float mu = s / 524288.f;
    const float var = s2 / 524288.f - mu * mu;
    g_stats[t * 2] = mu;
    g_stats[t * 2 + 1] = rsqrtf(var + 1e-5f);
}

// ============================================================
// Kernel 3: per-pixel epilogue. GN affine + exact GELU + 1x1 convs
// + sigmoid/CORN decode/normalize/labels.
// ============================================================
__global__ __launch_bounds__(256) void epilogue_kernel(
    const float* __restrict__ dgs, const float* __restrict__ dgb,
    const float* __restrict__ dw2, const float* __restrict__ db2,
    const float* __restrict__ sgs, const float* __restrict__ sgb,
    const float* __restrict__ sw2, const float* __restrict__ sb2,
    float* __restrict__ out)
{
    __shared__ float s_dgs[CH], s_dgb[CH], s_dw2[CH];
    __shared__ float s_sgs[CH], s_sgb[CH], s_sw0[CH], s_sw1[CH];
    __shared__ float s_mu[2][NGRP], s_rs[2][NGRP];

    const int tid = threadIdx.x;
    const int p   = blockIdx.x * 256 + tid;
    const int n   = p >> 14;
    const int pix = p & 16383;

    for (int c = tid; c < CH; c += 256) {
        s_dgs[c] = dgs[c]; s_dgb[c] = dgb[c]; s_dw2[c] = dw2[c];
        s_sgs[c] = sgs[c]; s_sgb[c] = sgb[c];
        s_sw0[c] = sw2[c]; s_sw1[c] = sw2[CH + c];
    }
    if (tid < 16) {
        int h = tid >> 3, g = tid & 7;
        int idx = ((h * BATCH + n) * NGRP + g) * 2;
        s_mu[h][g] = g_stats[idx];
        s_rs[h][g] = g_stats[idx + 1];
    }
    __syncthreads();

    const float* hd = g_hd + (size_t)n * CH * HW + pix;
    const float* hs = g_hs + (size_t)n * CH * HW + pix;

    float dl = 0.f, sl0 = 0.f, sl1 = 0.f;
#pragma unroll 4
    for (int c = 0; c < CH; c++) {
        const int g = c >> 5;
        float v  = hd[(size_t)c * HW];
        float xn = fmaf((v - s_mu[0][g]) * s_rs[0][g], s_dgs[c], s_dgb[c]);
        float ge = xn * normcdff(xn);
        dl = fmaf(ge, s_dw2[c], dl);

        v  = hs[(size_t)c * HW];
        xn = fmaf((v - s_mu[1][g]) * s_rs[1][g], s_sgs[c], s_sgb[c]);
        ge = xn * normcdff(xn);
        sl0 = fmaf(ge, s_sw0[c], sl0);
        sl1 = fmaf(ge, s_sw1[c], sl1);
    }
    dl  += db2[0];
    sl0 += sb2[0];
    sl1 += sb2[1];

    const float pd = 1.f / (1.f + expf(-dl));
    const float t0 = 1.f / (1.f + expf(-sl0));
    const float t1 = t0 * (1.f / (1.f + expf(-sl1)));
    float sev0 = fmaxf(1.f - t0, 1e-8f);
    float sev1 = fmaxf(t0 - t1, 1e-8f);
    float sev2 = fmaxf(t1,       1e-8f);
    const float ssum = fmaxf(sev0 + sev1 + sev2, 1e-8f);
    sev0 /= ssum; sev1 /= ssum; sev2 /= ssum;

    float px0 = fmaxf(1.f - pd,   1e-8f);
    float px1 = fmaxf(pd * sev0,  1e-8f);
    float px2 = fmaxf(pd * sev1,  1e-8f);
    float px3 = fmaxf(pd * sev2,  1e-8f);
    const float psum = fmaxf(px0 + px1 + px2 + px3, 1e-8f);
    px0 /= psum; px1 /= psum; px2 /= psum; px3 /= psum;

    int sp = 0; float bm = sev0;
    if (sev1 > bm) { bm = sev1; sp = 1; }
    if (sev2 > bm) { bm = sev2; sp = 2; }
    const int lbl = (pd >= 0.5f) ? (sp + 1) : 0;

    out[O_DMG  + n * HW + pix]            = dl;
    out[O_CORN + (n * 2 + 0) * HW + pix]  = sl0;
    out[O_CORN + (n * 2 + 1) * HW + pix]  = sl1;
    out[O_PIX  + (n * 4 + 0) * HW + pix]  = px0;
    out[O_PIX  + (n * 4 + 1) * HW + pix]  = px1;
    out[O_PIX  + (n * 4 + 2) * HW + pix]  = px2;
    out[O_PIX  + (n * 4 + 3) * HW + pix]  = px3;
    out[O_PRED + n * HW + pix]            = (float)lbl;
}

// ============================================================
// Kernel 4: masked mean + exact top-k sum per (b,c). 32 blocks.
// ============================================================
__global__ __launch_bounds__(256) void reduce_topk_kernel(
    const float* __restrict__ mask, const float* __restrict__ pix)
{
    extern __shared__ unsigned skey[];
    __shared__ int   ibuf[256];
    __shared__ float fbuf[256];

    const int tid = threadIdx.x;
    const int b = blockIdx.x >> 2;
    const int c = blockIdx.x & 3;
    const float* pv = pix  + ((size_t)b * 4 + c) * HW;
    const float* mk = mask + (size_t)b * HW;

    for (int i = tid; i < HW; i += 256)
        skey[i] = (mk[i] > 0.5f) ? __float_as_uint(pv[i]) : 0u;
    __syncthreads();

    int   mc = 0;
    float ms = 0.f;
    for (int i = tid; i < HW; i += 256) {
        unsigned kk = skey[i];
        if (kk) { mc++; ms += __uint_as_float(kk); }
    }
    ibuf[tid] = mc; fbuf[tid] = ms;
    __syncthreads();
    for (int off = 128; off > 0; off >>= 1) {
        if (tid < off) { ibuf[tid] += ibuf[tid + off]; fbuf[tid] += fbuf[tid + off]; }
        __syncthreads();
    }
    const int   cnt    = ibuf[0];
    const float sumall = fbuf[0];
    __syncthreads();

    int k = (int)rintf((float)cnt * 0.2f);
    if (k < 1) k = 1;
    const int cmax = (cnt > 1) ? cnt : 1;
    if (k > cmax) k = cmax;

    unsigned prefix = 0u;
    for (int bit = 30; bit >= 0; bit--) {
        const unsigned cand = prefix | (1u << bit);
        int cl = 0;
        for (int i = tid; i < HW; i += 256)
            if (skey[i] >= cand) cl++;
        ibuf[tid] = cl;
        __syncthreads();
        for (int off = 128; off > 0; off >>= 1) {
            if (tid < off) ibuf[tid] += ibuf[tid + off];
            __syncthreads();
        }
        if (ibuf[0] >= k) prefix = cand;
        __syncthreads();
    }

    int   cg = 0;
    float sg = 0.f;
    for (int i = tid; i < HW; i += 256) {
        unsigned kk = skey[i];
        if (kk > prefix) { cg++; sg += __uint_as_float(kk); }
    }
    ibuf[tid] = cg; fbuf[tid] = sg;
    __syncthreads();
    for (int off = 128; off > 0; off >>= 1) {
        if (tid < off) { ibuf[tid] += ibuf[tid + off]; fbuf[tid] += fbuf[tid + off]; }
        __syncthreads();
    }
    if (tid == 0) {
        const float T = __uint_as_float(prefix);
        const float topsum = fbuf[0] + (float)(k - ibuf[0]) * T;
        g_mean_raw[b * 4 + c] = sumall / (float)((cnt > 1) ? cnt : 1);
        g_topk_raw[b * 4 + c] = topsum / (float)k;
        g_cnt[b] = cnt;
    }
}

// ============================================================
// Kernel 5: finalize
// ============================================================
__global__ void finalize_kernel(float* __restrict__ out)
{
    const int b = threadIdx.x;
    if (b >= BATCH) return;
    const int cnt = g_cnt[b];

    float m[4], t[4], a[4];
    float sm = 0.f, st = 0.f;
    for (int c = 0; c < 4; c++) {
        m[c] = (cnt == 0) ? 0.25f : fmaxf(g_mean_raw[b * 4 + c], 1e-8f);
        t[c] = (cnt == 0) ? 0.25f : fmaxf(g_topk_raw[b * 4 + c], 1e-8f);
        sm += m[c]; st += t[c];
    }
    sm = fmaxf(sm, 1e-8f); st = fmaxf(st, 1e-8f);
    float sa = 0.f;
    for (int c = 0; c < 4; c++) {
        m[c] /= sm; t[c] /= st;
        a[c] = fmaxf(0.7f * m[c] + 0.3f * t[c], 1e-8f);
        sa += a[c];
    }
    sa = fmaxf(sa, 1e-8f);
    int best = 0; float bv = -1.f;
    for (int c = 0; c < 4; c++) {
        a[c] /= sa;
        if (a[c] > bv) { bv = a[c]; best = c; }
        out[O_MEAN + b * 4 + c] = m[c];
        out[O_TOPK + b * 4 + c] = t[c];
        out[O_AGG  + b * 4 + c] = a[c];
    }
    out[O_AGGL + b] = (float)best;
}

// ============================================================
extern "C" void kernel_launch(void* const* d_in, const int* in_sizes, int n_in,
                              void* d_out, int out_size)
{
    const float* fm   = (const float*)d_in[0];
    const float* mask = (const float*)d_in[1];
    const float* dw1  = (const float*)d_in[2];
    const float* dgs  = (const float*)d_in[3];
    const float* dgb  = (const float*)d_in[4];
    const float* dw2  = (const float*)d_in[5];
    const float* db2  = (const float*)d_in[6];
    const float* sw1  = (const float*)d_in[7];
    const float* sgs  = (const float*)d_in[8];
    const float* sgb  = (const float*)d_in[9];
    const float* sw2  = (const float*)d_in[10];
    const float* sb2  = (const float*)d_in[11];
    float* out = (float*)d_out;

    cudaFuncSetAttribute(conv_fp16_kernel,
                         cudaFuncAttributeMaxDynamicSharedMemorySize, 2 * STAGE_BYTES);
    cudaFuncSetAttribute(convert_in_kernel,
                         cudaFuncAttributeMaxDynamicSharedMemorySize, 128 * TP * 4);
    cudaFuncSetAttribute(reduce_topk_kernel,
                         cudaFuncAttributeMaxDynamicSharedMemorySize, HW * 4);

    convert_w_kernel<<<dim3(32, 9, 2), 256>>>(dw1, sw1);
    convert_in_kernel<<<dim3(2, 128, 8), 256, 128 * TP * 4>>>(fm);
    conv_fp16_kernel<<<dim3(4, 512), 512, 2 * STAGE_BYTES>>>();
    gn_partA_kernel<<<2048, 256>>>();
    gn_partB_kernel<<<1, 128>>>();
    epilogue_kernel<<<NPIX / 256, 256>>>(dgs, dgb, dw2, db2, sgs, sgb, sw2, sb2, out);
    reduce_topk_kernel<<<BATCH * 4, 256, HW * 4>>>(mask, out + O_PIX);
    finalize_kernel<<<1, 32>>>(out);
}

// round 12
// speedup vs baseline: 1.5476x; 1.5476x over previous
#include <cuda_runtime.h>
#include <cuda_fp16.h>
#include <math.h>
#include <stdint.h>

// Problem constants
#define BATCH 8
#define CIN   256
#define CH    256
#define HH    128
#define WW    128
#define HW    (HH*WW)          // 16384
#define NPIX  (BATCH*HW)       // 131072
#define NGRP  8
#define CPG   32

// Output layout (float32, tuple order, flattened+concatenated)
#define O_DMG   0
#define O_CORN  131072
#define O_PIX   393216
#define O_PRED  917504
#define O_MEAN  1048576
#define O_TOPK  1048608
#define O_AGG   1048640
#define O_AGGL  1048672

// -------- scratch (no cudaMalloc allowed) --------
__device__ float g_hd[(size_t)BATCH*CH*HW];          // damage conv3x3 out
__device__ float g_hs[(size_t)BATCH*CH*HW];          // severity conv3x3 out
// Weights, fp16 frag-permuted: [head][rs(9)][mg(16)][kk(16)][lane(32)] uint4
__device__ uint4 g_wah[2*9*16*16*32];
__device__ uint4 g_wal[2*9*16*16*32];
// Input, fp16 frag-permuted + pgp pair-packed, 3 x-shift planes:
// [s][n][pgp(1024)][kk(16)][lane(32)] uint4 = {b(pg even), b(pg odd)}
__device__ uint4 g_bah[(size_t)3*BATCH*1024*16*32];
__device__ uint4 g_bal[(size_t)3*BATCH*1024*16*32];
__device__ float g_part[2048*2];
__device__ float g_stats[2*BATCH*NGRP*2];
__device__ float g_mean_raw[BATCH*4];
__device__ float g_topk_raw[BATCH*4];
__device__ int   g_cnt[BATCH];

#define MMA_FP16(c, a, b0, b1) \
    asm volatile("mma.sync.aligned.m16n8k16.row.col.f32.f16.f16.f32 " \
        "{%0,%1,%2,%3},{%4,%5,%6,%7},{%8,%9},{%0,%1,%2,%3};" \
        : "+f"((c)[0]), "+f"((c)[1]), "+f"((c)[2]), "+f"((c)[3]) \
        : "r"((a).x), "r"((a).y), "r"((a).z), "r"((a).w), "r"(b0), "r"(b1))

#define CP_ASYNC16(dst, src) \
    asm volatile("cp.async.cg.shared.global [%0], [%1], 16;" :: "r"(dst), "l"(src) : "memory")
#define CP_ASYNC16P(dst, src, sz) \
    asm volatile("cp.async.cg.shared.global [%0], [%1], 16, %2;" :: "r"(dst), "l"(src), "r"(sz) : "memory")
#define CP_COMMIT()  asm volatile("cp.async.commit_group;" ::: "memory")
#define CP_WAIT1()   asm volatile("cp.async.wait_group 1;" ::: "memory")

__device__ __forceinline__ uint32_t pack_h2(float a, float b) {
    __half2 h = __halves2half2(__float2half_rn(a), __float2half_rn(b));
    return *reinterpret_cast<uint32_t*>(&h);
}

// ============================================================
// Kernel 0a: weight split into fp16 hi/lo, m16n8k16 frag-permuted.
// grid = (32, 9, 2), 256 thr.
// ============================================================
__global__ __launch_bounds__(256) void convert_w_kernel(
    const float* __restrict__ dw1, const float* __restrict__ sw1)
{
    const int i = blockIdx.x * 256 + threadIdx.x;    // 0..8191
    const int mg = i >> 9;
    const int kk = (i >> 5) & 15;
    const int l  = i & 31;
    const int g = l >> 2, tig = l & 3;
    const int head = blockIdx.z, rs = blockIdx.y;
    const int r = rs / 3, s = rs - r * 3;
    const float* w = head ? sw1 : dw1;

    const int co0 = mg * 16 + g;
    const int ciA = kk * 16 + 2 * tig;
    const int ciB = ciA + 8;

    float v[8];
    const int cos[8]  = {co0, co0, co0 + 8, co0 + 8, co0, co0, co0 + 8, co0 + 8};
    const int cis[8]  = {ciA, ciA + 1, ciA, ciA + 1, ciB, ciB + 1, ciB, ciB + 1};
#pragma unroll
    for (int q = 0; q < 8; q++)
        v[q] = w[((cos[q] * CIN + cis[q]) * 3 + r) * 3 + s];

    float h[8], lo[8];
#pragma unroll
    for (int q = 0; q < 8; q++) {
        h[q]  = __half2float(__float2half_rn(v[q]));
        lo[q] = v[q] - h[q];
    }
    uint4 hi4, lo4;
    hi4.x = pack_h2(h[0], h[1]);  lo4.x = pack_h2(lo[0], lo[1]);
    hi4.y = pack_h2(h[2], h[3]);  lo4.y = pack_h2(lo[2], lo[3]);
    hi4.z = pack_h2(h[4], h[5]);  lo4.z = pack_h2(lo[4], lo[5]);
    hi4.w = pack_h2(h[6], h[7]);  lo4.w = pack_h2(lo[6], lo[7]);
    const size_t off = (((size_t)(head * 9 + rs) * 16 + mg) * 16 + kk) * 32 + l;
    g_wah[off] = hi4;
    g_wal[off] = lo4;
}

// ============================================================
// Kernel 0b: input -> fp16 hi/lo frags via smem tile (coalesced).
// Block = (ci-half 128, one y-row). grid = (2, 128, 8), 256 thr.
// TP multiple of 4 so the float4 row writes stay 16B-aligned.
// ============================================================
#define TP 132
__global__ __launch_bounds__(256) void convert_in_kernel(const float* __restrict__ in)
{
    extern __shared__ float tile[];   // [128][TP]
    const int cihalf = blockIdx.x, y = blockIdx.y, n = blockIdx.z;
    const int ci0 = cihalf * 128;
    const int tid = threadIdx.x;

    // load 128 ci x 128 x, coalesced
    {
        const int c = tid >> 1, xs = (tid & 1) * 64;
        const float* src = in + ((size_t)(n * CIN + ci0 + c)) * HW + y * WW + xs;
        float* drow = tile + c * TP + xs;
        const float4* s4 = (const float4*)src;
#pragma unroll
        for (int j = 0; j < 16; j++)
            *(float4*)(drow + j * 4) = s4[j];
    }
    __syncthreads();

    const int kk_rel = tid >> 5;      // 0..7
    const int l = tid & 31;
    const int g = l >> 2, tig = l & 3;
    const int kk = cihalf * 8 + kk_rel;
    const int cb = kk_rel * 16 + 2 * tig;

#pragma unroll
    for (int pgp_rel = 0; pgp_rel < 8; pgp_rel++) {
        const int pgp = y * 8 + pgp_rel;
#pragma unroll
        for (int s = 0; s < 3; s++) {
            uint4 hi4, lo4;
            uint32_t* hp = &hi4.x;
            uint32_t* lp = &lo4.x;
#pragma unroll
            for (int pr = 0; pr < 2; pr++) {
                const int x = (pgp_rel * 2 + pr) * 8 + g;
                const int xp = x + s - 1;
                const bool ok = ((unsigned)xp < (unsigned)WW);
                float v0 = ok ? tile[cb * TP + xp]       : 0.f;
                float v1 = ok ? tile[(cb + 1) * TP + xp] : 0.f;
                float v2 = ok ? tile[(cb + 8) * TP + xp] : 0.f;
                float v3 = ok ? tile[(cb + 9) * TP + xp] : 0.f;
                float h0 = __half2float(__float2half_rn(v0));
                float h1 = __half2float(__float2half_rn(v1));
                float h2 = __half2float(__float2half_rn(v2));
                float h3 = __half2float(__float2half_rn(v3));
                hp[pr * 2]     = pack_h2(h0, h1);
                hp[pr * 2 + 1] = pack_h2(h2, h3);
                lp[pr * 2]     = pack_h2(v0 - h0, v1 - h1);
                lp[pr * 2 + 1] = pack_h2(v2 - h2, v3 - h3);
            }
            const size_t off = (((size_t)(s * BATCH + n) * 1024 + pgp) * 16 + kk) * 32 + l;
            g_bah[off] = hi4;
            g_bal[off] = lo4;
        }
    }
}

// ============================================================
// Kernel 1: conv3x3 via 3-term fp16-split m16n8k16 implicit GEMM.
// R7-proven shape: CTA = 128co x 256px, 8 warps (2m x 4n) of 64x64,
// 256 threads, 36 stages (9 rs x 4), K=64/stage, 2-stage cp.async.
// B is pgp pair-packed: one LDS.128 feeds two n8 MMAs.
// grid = dim3(4, 512); blockIdx.x = head*2+cotile.
// ============================================================
#define STAGE_BYTES 98304   // Ah 16K | Al 16K | Bh 32K | Bl 32K
#define A_LO_OFF 16384
#define B_HI_OFF 32768
#define B_LO_OFF 65536

__device__ __forceinline__ void stage_load(
    char* sp, int st, int head, int cotile, int sn_base, int pgp0, int tid)
{
    const int rs  = st >> 2;
    const int kk0 = (st & 3) * 4;
    const int r = rs / 3, s = rs - r * 3;

    // A: 2048 uint4 (hi 1024 + lo 1024), 8 per thread
    const size_t abase = (((size_t)(head * 9 + rs) * 16 + cotile * 8) * 16 + kk0) * 32;
#pragma unroll
    for (int it = 0; it < 8; it++) {
        const int cid = tid + it * 256;
        const int prec = cid >> 10, cc = cid & 1023;
        const int mgl = cc >> 7, kkl = (cc >> 5) & 3, ll = cc & 31;
        const uint4* src = (prec ? g_wal : g_wah) + abase + mgl * 512 + kkl * 32 + ll;
        uint32_t dst = (uint32_t)__cvta_generic_to_shared(
            sp + prec * A_LO_OFF + ((mgl * 4 + kkl) * 32 + ll) * 16);
        CP_ASYNC16(dst, src);
    }
    // B: 4096 uint4 (hi+lo), 16 per thread; pgp row-shift predicate
    const size_t bbase = ((size_t)(s * BATCH + sn_base)) * 1024;
    const int pgpsh = pgp0 + (r - 1) * 8;
#pragma unroll
    for (int it = 0; it < 16; it++) {
        const int cid = tid + it * 256;
        const int prec = cid >> 11, cc = cid & 2047;
        const int kkl = cc >> 9, pgl = (cc >> 5) & 15, ll = cc & 31;
        const int pgpsrc = pgpsh + pgl;
        const unsigned ok = ((unsigned)pgpsrc < 1024u);
        const int pgpc = ok ? pgpsrc : 0;
        const uint4* src = (prec ? g_bal : g_bah)
            + ((bbase + pgpc) * 16 + kk0 + kkl) * 32 + ll;
        uint32_t dst = (uint32_t)__cvta_generic_to_shared(
            sp + B_HI_OFF + prec * 32768 + ((kkl * 16 + pgl) * 32 + ll) * 16);
        CP_ASYNC16P(dst, src, ok ? 16u : 0u);
    }
}

__global__ __launch_bounds__(256, 1) void conv_fp16_kernel()
{
    extern __shared__ char smem[];
    const int tid = threadIdx.x;
    const int lane = tid & 31;
    const int wid = tid >> 5;
    const int warp_m = wid >> 2;       // 0..1 -> 64 co
    const int warp_n = wid & 3;        // 0..3 -> 64 px
    const int g = lane >> 2, tig = lane & 3;

    const int head   = blockIdx.x >> 1;
    const int cotile = blockIdx.x & 1;
    const int ptile  = blockIdx.y;     // 0..511
    const int n      = ptile >> 6;
    const int pix0   = (ptile & 63) * 256;
    const int pgp0   = (ptile & 63) * 16;

    float c[4][8][4];
#pragma unroll
    for (int m = 0; m < 4; m++)
#pragma unroll
        for (int nn = 0; nn < 8; nn++)
#pragma unroll
            for (int q = 0; q < 4; q++) c[m][nn][q] = 0.f;

    char* buf0 = smem;
    char* buf1 = smem + STAGE_BYTES;

    stage_load(buf0, 0, head, cotile, n, pgp0, tid); CP_COMMIT();
    stage_load(buf1, 1, head, cotile, n, pgp0, tid); CP_COMMIT();

    for (int st = 0; st < 36; st++) {
        CP_WAIT1();
        __syncthreads();
        char* sp = (st & 1) ? buf1 : buf0;

#pragma unroll
        for (int kkl = 0; kkl < 4; kkl++) {
            uint4 Ah[4], Al[4];
#pragma unroll
            for (int m = 0; m < 4; m++) {
                const int mgl = warp_m * 4 + m;
                Ah[m] = *(const uint4*)(sp + ((mgl * 4 + kkl) * 32 + lane) * 16);
                Al[m] = *(const uint4*)(sp + A_LO_OFF + ((mgl * 4 + kkl) * 32 + lane) * 16);
            }
#pragma unroll
            for (int np = 0; np < 4; np++) {
                const int pgp_l = warp_n * 4 + np;
                uint4 bh = *(const uint4*)(sp + B_HI_OFF + ((kkl * 16 + pgp_l) * 32 + lane) * 16);
                uint4 bl = *(const uint4*)(sp + B_LO_OFF + ((kkl * 16 + pgp_l) * 32 + lane) * 16);
#pragma unroll
                for (int m = 0; m < 4; m++) {
                    MMA_FP16(c[m][np * 2],     Ah[m], bh.x, bh.y);
                    MMA_FP16(c[m][np * 2],     Al[m], bh.x, bh.y);
                    MMA_FP16(c[m][np * 2],     Ah[m], bl.x, bl.y);
                    MMA_FP16(c[m][np * 2 + 1], Ah[m], bh.z, bh.w);
                    MMA_FP16(c[m][np * 2 + 1], Al[m], bh.z, bh.w);
                    MMA_FP16(c[m][np * 2 + 1], Ah[m], bl.z, bl.w);
                }
            }
        }
        __syncthreads();
        if (st + 2 < 36)
            stage_load((st & 1) ? buf1 : buf0, st + 2, head, cotile, n, pgp0, tid);
        CP_COMMIT();
    }

    // store to g_hd / g_hs [n][co][pix]
    float* outb = head ? g_hs : g_hd;
#pragma unroll
    for (int m = 0; m < 4; m++) {
        const int co = cotile * 128 + (warp_m * 4 + m) * 16 + g;
        float* orow = outb + ((size_t)(n * CH + co)) * HW;
#pragma unroll
        for (int n8 = 0; n8 < 8; n8++) {
            const int pixl = pix0 + warp_n * 64 + n8 * 8 + tig * 2;
            *(float2*)(orow + pixl)                  = make_float2(c[m][n8][0], c[m][n8][1]);
            *(float2*)(orow + (size_t)8 * HW + pixl) = make_float2(c[m][n8][2], c[m][n8][3]);
        }
    }
}

// ============================================================
// Kernel 2a/2b: GroupNorm stats, two-phase.
// ============================================================
__global__ __launch_bounds__(256) void gn_partA_kernel()
{
    const int id = blockIdx.x;               // ((head*8+b)*8+g)*16+slice
    const int head = id >> 10;
    const int b = (id >> 7) & 7;
    const int g = (id >> 4) & 7;
    const int sl = id & 15;
    const float4* p4 = (const float4*)((head ? g_hs : g_hd)
                     + ((size_t)(b * CH + g * CPG)) * HW + sl * 32768);
    const int tid = threadIdx.x;
    float s = 0.f, s2 = 0.f;
    for (int i = tid; i < 8192; i += 256) {
        float4 v = p4[i];
        s += (v.x + v.y) + (v.z + v.w);
        s2 = fmaf(v.x, v.x, fmaf(v.y, v.y, fmaf(v.z, v.z, fmaf(v.w, v.w, s2))));
    }
    __shared__ float sh[256], sh2[256];
    sh[tid] = s; sh2[tid] = s2;
    __syncthreads();
    for (int off = 128; off > 0; off >>= 1) {
        if (tid < off) { sh[tid] += sh[tid + off]; sh2[tid] += sh2[tid + off]; }
        __syncthreads();
    }
    if (tid == 0) { g_part[id * 2] = sh[0]; g_part[id * 2 + 1] = sh2[0]; }
}

__global__ void gn_partB_kernel()
{
    const int t = threadIdx.x;
    if (t >= 128) return;
    float s = 0.f, s2 = 0.f;
    for (int i = 0; i < 16; i++) {
        s  += g_part[(t * 16 + i) * 2];
        s2 += g_part[(t * 16 + i) * 2 + 1];
    }
    const float mu = s / 524288.f;
    const float var = s2 / 524288.f - mu * mu;
    g_stats[t * 2] = mu;
    g_stats[t * 2 + 1] = rsqrtf(var + 1e-5f);
}

// ============================================================
// Kernel 3: per-pixel epilogue. GN affine + exact GELU + 1x1 convs
// + sigmoid/CORN decode/normalize/labels.
// ============================================================
__global__ __launch_bounds__(256) void epilogue_kernel(
    const float* __restrict__ dgs, const float* __restrict__ dgb,
    const float* __restrict__ dw2, const float* __restrict__ db2,
    const float* __restrict__ sgs, const float* __restrict__ sgb,
    const float* __restrict__ sw2, const float* __restrict__ sb2,
    float* __restrict__ out)
{
    __shared__ float s_dgs[CH], s_dgb[CH], s_dw2[CH];
    __shared__ float s_sgs[CH], s_sgb[CH], s_sw0[CH], s_sw1[CH];
    __shared__ float s_mu[2][NGRP], s_rs[2][NGRP];

    const int tid = threadIdx.x;
    const int p   = blockIdx.x * 256 + tid;
    const int n   = p >> 14;
    const int pix = p & 16383;

    for (int c = tid; c < CH; c += 256) {
        s_dgs[c] = dgs[c]; s_dgb[c] = dgb[c]; s_dw2[c] = dw2[c];
        s_sgs[c] = sgs[c]; s_sgb[c] = sgb[c];
        s_sw0[c] = sw2[c]; s_sw1[c] = sw2[CH + c];
    }
    if (tid < 16) {
        int h = tid >> 3, g = tid & 7;
        int idx = ((h * BATCH + n) * NGRP + g) * 2;
        s_mu[h][g] = g_stats[idx];
        s_rs[h][g] = g_stats[idx + 1];
    }
    __syncthreads();

    const float* hd = g_hd + (size_t)n * CH * HW + pix;
    const float* hs = g_hs + (size_t)n * CH * HW + pix;

    float dl = 0.f, sl0 = 0.f, sl1 = 0.f;
#pragma unroll 4
    for (int c = 0; c < CH; c++) {
        const int g = c >> 5;
        float v  = hd[(size_t)c * HW];
        float xn = fmaf((v - s_mu[0][g]) * s_rs[0][g], s_dgs[c], s_dgb[c]);
        float ge = xn * normcdff(xn);
        dl = fmaf(ge, s_dw2[c], dl);

        v  = hs[(size_t)c * HW];
        xn = fmaf((v - s_mu[1][g]) * s_rs[1][g], s_sgs[c], s_sgb[c]);
        ge = xn * normcdff(xn);
        sl0 = fmaf(ge, s_sw0[c], sl0);
        sl1 = fmaf(ge, s_sw1[c], sl1);
    }
    dl  += db2[0];
    sl0 += sb2[0];
    sl1 += sb2[1];

    const float pd = 1.f / (1.f + expf(-dl));
    const float t0 = 1.f / (1.f + expf(-sl0));
    const float t1 = t0 * (1.f / (1.f + expf(-sl1)));
    float sev0 = fmaxf(1.f - t0, 1e-8f);
    float sev1 = fmaxf(t0 - t1, 1e-8f);
    float sev2 = fmaxf(t1,       1e-8f);
    const float ssum = fmaxf(sev0 + sev1 + sev2, 1e-8f);
    sev0 /= ssum; sev1 /= ssum; sev2 /= ssum;

    float px0 = fmaxf(1.f - pd,   1e-8f);
    float px1 = fmaxf(pd * sev0,  1e-8f);
    float px2 = fmaxf(pd * sev1,  1e-8f);
    float px3 = fmaxf(pd * sev2,  1e-8f);
    const float psum = fmaxf(px0 + px1 + px2 + px3, 1e-8f);
    px0 /= psum; px1 /= psum; px2 /= psum; px3 /= psum;

    int sp = 0; float bm = sev0;
    if (sev1 > bm) { bm = sev1; sp = 1; }
    if (sev2 > bm) { bm = sev2; sp = 2; }
    const int lbl = (pd >= 0.5f) ? (sp + 1) : 0;

    out[O_DMG  + n * HW + pix]            = dl;
    out[O_CORN + (n * 2 + 0) * HW + pix]  = sl0;
    out[O_CORN + (n * 2 + 1) * HW + pix]  = sl1;
    out[O_PIX  + (n * 4 + 0) * HW + pix]  = px0;
    out[O_PIX  + (n * 4 + 1) * HW + pix]  = px1;
    out[O_PIX  + (n * 4 + 2) * HW + pix]  = px2;
    out[O_PIX  + (n * 4 + 3) * HW + pix]  = px3;
    out[O_PRED + n * HW + pix]            = (float)lbl;
}

// ============================================================
// Kernel 4: masked mean + exact top-k sum per (b,c). 32 blocks.
// ============================================================
__global__ __launch_bounds__(256) void reduce_topk_kernel(
    const float* __restrict__ mask, const float* __restrict__ pix)
{
    extern __shared__ unsigned skey[];
    __shared__ int   ibuf[256];
    __shared__ float fbuf[256];

    const int tid = threadIdx.x;
    const int b = blockIdx.x >> 2;
    const int c = blockIdx.x & 3;
    const float* pv = pix  + ((size_t)b * 4 + c) * HW;
    const float* mk = mask + (size_t)b * HW;

    for (int i = tid; i < HW; i += 256)
        skey[i] = (mk[i] > 0.5f) ? __float_as_uint(pv[i]) : 0u;
    __syncthreads();

    int   mc = 0;
    float ms = 0.f;
    for (int i = tid; i < HW; i += 256) {
        unsigned kk = skey[i];
        if (kk) { mc++; ms += __uint_as_float(kk); }
    }
    ibuf[tid] = mc; fbuf[tid] = ms;
    __syncthreads();
    for (int off = 128; off > 0; off >>= 1) {
        if (tid < off) { ibuf[tid] += ibuf[tid + off]; fbuf[tid] += fbuf[tid + off]; }
        __syncthreads();
    }
    const int   cnt    = ibuf[0];
    const float sumall = fbuf[0];
    __syncthreads();

    int k = (int)rintf((float)cnt * 0.2f);
    if (k < 1) k = 1;
    const int cmax = (cnt > 1) ? cnt : 1;
    if (k > cmax) k = cmax;

    unsigned prefix = 0u;
    for (int bit = 30; bit >= 0; bit--) {
        const unsigned cand = prefix | (1u << bit);
        int cl = 0;
        for (int i = tid; i < HW; i += 256)
            if (skey[i] >= cand) cl++;
        ibuf[tid] = cl;
        __syncthreads();
        for (int off = 128; off > 0; off >>= 1) {
            if (tid < off) ibuf[tid] += ibuf[tid + off];
            __syncthreads();
        }
        if (ibuf[0] >= k) prefix = cand;
        __syncthreads();
    }

    int   cg = 0;
    float sg = 0.f;
    for (int i = tid; i < HW; i += 256) {
        unsigned kk = skey[i];
        if (kk > prefix) { cg++; sg += __uint_as_float(kk); }
    }
    ibuf[tid] = cg; fbuf[tid] = sg;
    __syncthreads();
    for (int off = 128; off > 0; off >>= 1) {
        if (tid < off) { ibuf[tid] += ibuf[tid + off]; fbuf[tid] += fbuf[tid + off]; }
        __syncthreads();
    }
    if (tid == 0) {
        const float T = __uint_as_float(prefix);
        const float topsum = fbuf[0] + (float)(k - ibuf[0]) * T;
        g_mean_raw[b * 4 + c] = sumall / (float)((cnt > 1) ? cnt : 1);
        g_topk_raw[b * 4 + c] = topsum / (float)k;
        g_cnt[b] = cnt;
    }
}

// ============================================================
// Kernel 5: finalize
// ============================================================
__global__ void finalize_kernel(float* __restrict__ out)
{
    const int b = threadIdx.x;
    if (b >= BATCH) return;
    const int cnt = g_cnt[b];

    float m[4], t[4], a[4];
    float sm = 0.f, st = 0.f;
    for (int c = 0; c < 4; c++) {
        m[c] = (cnt == 0) ? 0.25f : fmaxf(g_mean_raw[b * 4 + c], 1e-8f);
        t[c] = (cnt == 0) ? 0.25f : fmaxf(g_topk_raw[b * 4 + c], 1e-8f);
        sm += m[c]; st += t[c];
    }
    sm = fmaxf(sm, 1e-8f); st = fmaxf(st, 1e-8f);
    float sa = 0.f;
    for (int c = 0; c < 4; c++) {
        m[c] /= sm; t[c] /= st;
        a[c] = fmaxf(0.7f * m[c] + 0.3f * t[c], 1e-8f);
        sa += a[c];
    }
    sa = fmaxf(sa, 1e-8f);
    int best = 0; float bv = -1.f;
    for (int c = 0; c < 4; c++) {
        a[c] /= sa;
        if (a[c] > bv) { bv = a[c]; best = c; }
        out[O_MEAN + b * 4 + c] = m[c];
        out[O_TOPK + b * 4 + c] = t[c];
        out[O_AGG  + b * 4 + c] = a[c];
    }
    out[O_AGGL + b] = (float)best;
}

// ============================================================
extern "C" void kernel_launch(void* const* d_in, const int* in_sizes, int n_in,
                              void* d_out, int out_size)
{
    const float* fm   = (const float*)d_in[0];
    const float* mask = (const float*)d_in[1];
    const float* dw1  = (const float*)d_in[2];
    const float* dgs  = (const float*)d_in[3];
    const float* dgb  = (const float*)d_in[4];
    const float* dw2  = (const float*)d_in[5];
    const float* db2  = (const float*)d_in[6];
    const float* sw1  = (const float*)d_in[7];
    const float* sgs  = (const float*)d_in[8];
    const float* sgb  = (const float*)d_in[9];
    const float* sw2  = (const float*)d_in[10];
    const float* sb2  = (const float*)d_in[11];
    float* out = (float*)d_out;

    cudaFuncSetAttribute(conv_fp16_kernel,
                         cudaFuncAttributeMaxDynamicSharedMemorySize, 2 * STAGE_BYTES);
    cudaFuncSetAttribute(convert_in_kernel,
                         cudaFuncAttributeMaxDynamicSharedMemorySize, 128 * TP * 4);
    cudaFuncSetAttribute(reduce_topk_kernel,
                         cudaFuncAttributeMaxDynamicSharedMemorySize, HW * 4);

    convert_w_kernel<<<dim3(32, 9, 2), 256>>>(dw1, sw1);
    convert_in_kernel<<<dim3(2, 128, 8), 256, 128 * TP * 4>>>(fm);
    conv_fp16_kernel<<<dim3(4, 512), 256, 2 * STAGE_BYTES>>>();
    gn_partA_kernel<<<2048, 256>>>();
    gn_partB_kernel<<<1, 128>>>();
    epilogue_kernel<<<NPIX / 256, 256>>>(dgs, dgb, dw2, db2, sgs, sgb, sw2, sb2, out);
    reduce_topk_kernel<<<BATCH * 4, 256, HW * 4>>>(mask, out + O_PIX);
    finalize_kernel<<<1, 32>>>(out);
}

// round 13
// speedup vs baseline: 1.7386x; 1.1234x over previous
#include <cuda_runtime.h>
#include <cuda_fp16.h>
#include <math.h>
#include <stdint.h>

// Problem constants
#define BATCH 8
#define CIN   256
#define CH    256
#define HH    128
#define WW    128
#define HW    (HH*WW)          // 16384
#define NPIX  (BATCH*HW)       // 131072
#define NGRP  8
#define CPG   32

// Output layout (float32, tuple order, flattened+concatenated)
#define O_DMG   0
#define O_CORN  131072
#define O_PIX   393216
#define O_PRED  917504
#define O_MEAN  1048576
#define O_TOPK  1048608
#define O_AGG   1048640
#define O_AGGL  1048672

// -------- scratch (no cudaMalloc allowed) --------
__device__ float g_hd[(size_t)BATCH*CH*HW];          // damage conv3x3 out
__device__ float g_hs[(size_t)BATCH*CH*HW];          // severity conv3x3 out
// Winograd weights, fp16 frag-permuted:
// plane = (head*4+comp)*3 + r ; [plane][mg(16)][kk(16)][lane(32)] uint4
__device__ uint4 g_wah[2*4*3*16*16*32];
__device__ uint4 g_wal[2*4*3*16*16*32];
// Winograd input components, fp16 frag-permuted:
// [(comp*BATCH+n)][pg(1024)][kk(16)][lane(32)] uint2  (pair-group of 8 pairs)
__device__ uint2 g_bh[(size_t)4*BATCH*1024*16*32];
__device__ uint2 g_bl[(size_t)4*BATCH*1024*16*32];
__device__ float g_part[2048*2];
__device__ float g_stats[2*BATCH*NGRP*2];
__device__ float g_mean_raw[BATCH*4];
__device__ float g_topk_raw[BATCH*4];
__device__ int   g_cnt[BATCH];

#define MMA_FP16(c, a, b0, b1) \
    asm volatile("mma.sync.aligned.m16n8k16.row.col.f32.f16.f16.f32 " \
        "{%0,%1,%2,%3},{%4,%5,%6,%7},{%8,%9},{%0,%1,%2,%3};" \
        : "+f"((c)[0]), "+f"((c)[1]), "+f"((c)[2]), "+f"((c)[3]) \
        : "r"((a).x), "r"((a).y), "r"((a).z), "r"((a).w), "r"(b0), "r"(b1))

#define CP_ASYNC16(dst, src) \
    asm volatile("cp.async.cg.shared.global [%0], [%1], 16;" :: "r"(dst), "l"(src) : "memory")
#define CP_ASYNC8P(dst, src, sz) \
    asm volatile("cp.async.ca.shared.global [%0], [%1], 8, %2;" :: "r"(dst), "l"(src), "r"(sz) : "memory")
#define CP_COMMIT()  asm volatile("cp.async.commit_group;" ::: "memory")
#define CP_WAIT1()   asm volatile("cp.async.wait_group 1;" ::: "memory")

__device__ __forceinline__ uint32_t pack_h2(float a, float b) {
    __half2 h = __halves2half2(__float2half_rn(a), __float2half_rn(b));
    return *reinterpret_cast<uint32_t*>(&h);
}

// ============================================================
// Kernel 0a: Winograd weight transform + fp16 hi/lo split,
// m16n8k16 frag-permuted. grid = (32, 12, 2) [y = comp*3+r].
// G0=g0, G1=(g0+g1+g2)/2, G2=(g0-g1+g2)/2, G3=g2.
// ============================================================
__global__ __launch_bounds__(256) void convert_w_kernel(
    const float* __restrict__ dw1, const float* __restrict__ sw1)
{
    const int i = blockIdx.x * 256 + threadIdx.x;    // 0..8191
    const int mg = i >> 9;
    const int kk = (i >> 5) & 15;
    const int l  = i & 31;
    const int g = l >> 2, tig = l & 3;
    const int head = blockIdx.z;
    const int comp = blockIdx.y / 3, r = blockIdx.y - comp * 3;
    const float* w = head ? sw1 : dw1;

    const int co0 = mg * 16 + g;
    const int ciA = kk * 16 + 2 * tig;
    const int ciB = ciA + 8;

    const int cos[8]  = {co0, co0, co0 + 8, co0 + 8, co0, co0, co0 + 8, co0 + 8};
    const int cis[8]  = {ciA, ciA + 1, ciA, ciA + 1, ciB, ciB + 1, ciB, ciB + 1};

    float v[8];
#pragma unroll
    for (int q = 0; q < 8; q++) {
        const float* wp = w + ((size_t)(cos[q] * CIN + cis[q]) * 3 + r) * 3;
        float w0 = wp[0], w1 = wp[1], w2 = wp[2];
        float G;
        if      (comp == 0) G = w0;
        else if (comp == 1) G = 0.5f * (w0 + w1 + w2);
        else if (comp == 2) G = 0.5f * (w0 - w1 + w2);
        else                G = w2;
        v[q] = G;
    }
    float h[8], lo[8];
#pragma unroll
    for (int q = 0; q < 8; q++) {
        h[q]  = __half2float(__float2half_rn(v[q]));
        lo[q] = v[q] - h[q];
    }
    uint4 hi4, lo4;
    hi4.x = pack_h2(h[0], h[1]);  lo4.x = pack_h2(lo[0], lo[1]);
    hi4.y = pack_h2(h[2], h[3]);  lo4.y = pack_h2(lo[2], lo[3]);
    hi4.z = pack_h2(h[4], h[5]);  lo4.z = pack_h2(lo[4], lo[5]);
    hi4.w = pack_h2(h[6], h[7]);  lo4.w = pack_h2(lo[6], lo[7]);
    const size_t off = (((size_t)((head * 4 + comp) * 3 + r) * 16 + mg) * 16 + kk) * 32 + l;
    g_wah[off] = hi4;
    g_wal[off] = lo4;
}

// ============================================================
// Kernel 0b: input -> Winograd components c0..c3 per x-pair,
// fp16 hi/lo split, frag-permuted. Block = (ci-half, y-row).
// grid = (2, 128, 8), 256 thr. c0=d0-d2, c1=d1+d2, c2=d2-d1,
// c3=d1-d3 with d = in at x = 2t-1..2t+2 (zero pad at edges).
// ============================================================
#define TP 132
__global__ __launch_bounds__(256) void convert_in_kernel(const float* __restrict__ in)
{
    extern __shared__ float tile[];   // [128][TP]
    const int cihalf = blockIdx.x, y = blockIdx.y, n = blockIdx.z;
    const int ci0 = cihalf * 128;
    const int tid = threadIdx.x;

    // load 128 ci x 128 x, coalesced
    {
        const int c = tid >> 1, xs = (tid & 1) * 64;
        const float* src = in + ((size_t)(n * CIN + ci0 + c)) * HW + y * WW + xs;
        float* drow = tile + c * TP + xs;
        const float4* s4 = (const float4*)src;
#pragma unroll
        for (int j = 0; j < 16; j++)
            *(float4*)(drow + j * 4) = s4[j];
    }
    __syncthreads();

    const int kk_rel = tid >> 5;      // 0..7
    const int l = tid & 31;
    const int g = l >> 2, tig = l & 3;
    const int kk = cihalf * 8 + kk_rel;
    const int cb = kk_rel * 16 + 2 * tig;
    const int cs[4] = {cb, cb + 1, cb + 8, cb + 9};

#pragma unroll
    for (int pg_rel = 0; pg_rel < 8; pg_rel++) {
        const int t = pg_rel * 8 + g;        // pair index within row, 0..63
        const int x0 = 2 * t;
        float comp_v[4][4];                  // [comp][ci-slot]
#pragma unroll
        for (int q = 0; q < 4; q++) {
            const float* row = tile + cs[q] * TP;
            float d0 = (t > 0)  ? row[x0 - 1] : 0.f;
            float d1 = row[x0];
            float d2 = row[x0 + 1];
            float d3 = (t < 63) ? row[x0 + 2] : 0.f;
            comp_v[0][q] = d0 - d2;
            comp_v[1][q] = d1 + d2;
            comp_v[2][q] = d2 - d1;
            comp_v[3][q] = d1 - d3;
        }
        const int pg = y * 8 + pg_rel;
#pragma unroll
        for (int comp = 0; comp < 4; comp++) {
            float h[4], lo[4];
#pragma unroll
            for (int q = 0; q < 4; q++) {
                h[q]  = __half2float(__float2half_rn(comp_v[comp][q]));
                lo[q] = comp_v[comp][q] - h[q];
            }
            uint2 hi2, lo2;
            hi2.x = pack_h2(h[0], h[1]);  lo2.x = pack_h2(lo[0], lo[1]);
            hi2.y = pack_h2(h[2], h[3]);  lo2.y = pack_h2(lo[2], lo[3]);
            const size_t off = (((size_t)(comp * BATCH + n) * 1024 + pg) * 16 + kk) * 32 + l;
            g_bh[off] = hi2;
            g_bl[off] = lo2;
        }
    }
}

// ============================================================
// Kernel 1: conv3x3 via 1D-Winograd F(2,3) + 3-term fp16-split
// m16n8k16 GEMMs. CTA = 128co x 64 pairs (one y-row), 8 warps
// (2m x 4n) of 64co x 16 pairs. 4 components x 12 K-chunks
// (K=768 = r(3) x ci(256)) = 48 stages, 2-stage cp.async,
// 48KB/stage. grid = dim3(4, 1024).
// ============================================================
#define STAGE_BYTES 49152   // Ah 16K | Al 16K | Bh 8K | Bl 8K
#define A_LO_OFF 16384
#define B_HI_OFF 32768
#define B_LO_OFF 40960

__device__ __forceinline__ void stage_load(
    char* sp, int cn, int tn, int head, int cotile, int n, int pg0, int tid)
{
    const int r   = tn >> 2;
    const int kk0 = (tn & 3) * 4;

    // A: 2048 uint4 (hi 1024 + lo 1024), 8 per thread
    const size_t abase = ((size_t)((head * 4 + cn) * 3 + r) * 16 + cotile * 8) * 512;
#pragma unroll
    for (int it = 0; it < 8; it++) {
        const int cid = tid + it * 256;
        const int prec = cid >> 10, cc = cid & 1023;
        const int mgl = cc >> 7, kkl = (cc >> 5) & 3, ll = cc & 31;
        const uint4* src = (prec ? g_wal : g_wah) + abase + mgl * 512 + (kk0 + kkl) * 32 + ll;
        uint32_t dst = (uint32_t)__cvta_generic_to_shared(
            sp + prec * A_LO_OFF + ((mgl * 4 + kkl) * 32 + ll) * 16);
        CP_ASYNC16(dst, src);
    }
    // B: 2048 uint2 (hi 1024 + lo 1024), 8 per thread; row-shift predicate
    const size_t bbase = (size_t)(cn * BATCH + n) * 1024;
    const int pgsh = pg0 + (r - 1) * 8;
#pragma unroll
    for (int it = 0; it < 8; it++) {
        const int cid = tid + it * 256;
        const int prec = cid >> 10, cc = cid & 1023;
        const int kkl = cc >> 8, pgl = (cc >> 5) & 7, ll = cc & 31;
        const int pgsrc = pgsh + pgl;
        const unsigned ok = ((unsigned)pgsrc < 1024u);
        const int pgc = ok ? pgsrc : 0;
        const uint2* src = (prec ? g_bl : g_bh)
            + ((bbase + pgc) * 16 + kk0 + kkl) * 32 + ll;
        uint32_t dst = (uint32_t)__cvta_generic_to_shared(
            sp + B_HI_OFF + prec * 8192 + ((kkl * 8 + pgl) * 32 + ll) * 8);
        CP_ASYNC8P(dst, src, ok ? 8u : 0u);
    }
}

__global__ __launch_bounds__(256, 1) void conv_wino_kernel()
{
    extern __shared__ char smem[];
    const int tid = threadIdx.x;
    const int lane = tid & 31;
    const int wid = tid >> 5;
    const int warp_m = wid >> 2;       // 0..1 -> 64 co
    const int warp_n = wid & 3;        // 0..3 -> 16 pairs
    const int g = lane >> 2, tig = lane & 3;

    const int head   = blockIdx.x >> 1;
    const int cotile = blockIdx.x & 1;
    const int ptile  = blockIdx.y;     // 0..1023
    const int n      = ptile >> 7;     // image
    const int row    = ptile & 127;    // y
    const int pg0    = row * 8;        // pair-group base (8 pg per row)

    float acc[4][4][2][4];             // [comp][m][np][q]
#pragma unroll
    for (int c4 = 0; c4 < 4; c4++)
#pragma unroll
        for (int m = 0; m < 4; m++)
#pragma unroll
            for (int np = 0; np < 2; np++)
#pragma unroll
                for (int q = 0; q < 4; q++) acc[c4][m][np][q] = 0.f;

    char* buf0 = smem;
    char* buf1 = smem + STAGE_BYTES;

    stage_load(buf0, 0, 0, head, cotile, n, pg0, tid); CP_COMMIT();
    stage_load(buf1, 0, 1, head, cotile, n, pg0, tid); CP_COMMIT();

#pragma unroll
    for (int comp = 0; comp < 4; comp++) {
        for (int t = 0; t < 12; t++) {
            const int sidx = comp * 12 + t;
            CP_WAIT1();
            __syncthreads();
            char* sp = (sidx & 1) ? buf1 : buf0;

#pragma unroll
            for (int kkl = 0; kkl < 4; kkl++) {
                uint4 Ah[4], Al[4];
#pragma unroll
                for (int m = 0; m < 4; m++) {
                    const int mgl = warp_m * 4 + m;
                    Ah[m] = *(const uint4*)(sp + ((mgl * 4 + kkl) * 32 + lane) * 16);
                    Al[m] = *(const uint4*)(sp + A_LO_OFF + ((mgl * 4 + kkl) * 32 + lane) * 16);
                }
#pragma unroll
                for (int np = 0; np < 2; np++) {
                    const int pgl = warp_n * 2 + np;
                    uint2 bh = *(const uint2*)(sp + B_HI_OFF + ((kkl * 8 + pgl) * 32 + lane) * 8);
                    uint2 bl = *(const uint2*)(sp + B_LO_OFF + ((kkl * 8 + pgl) * 32 + lane) * 8);
#pragma unroll
                    for (int m = 0; m < 4; m++) {
                        MMA_FP16(acc[comp][m][np], Ah[m], bh.x, bh.y);
                        MMA_FP16(acc[comp][m][np], Al[m], bh.x, bh.y);
                        MMA_FP16(acc[comp][m][np], Ah[m], bl.x, bl.y);
                    }
                }
            }
            __syncthreads();
            if (sidx + 2 < 48) {
                int tn = t + 2, cn = comp;
                if (tn >= 12) { tn -= 12; cn += 1; }
                stage_load((sidx & 1) ? buf1 : buf0, cn, tn, head, cotile, n, pg0, tid);
            }
            CP_COMMIT();
        }
    }

    // Winograd recombine + store: y0 = A0+A1+A2, y1 = A1-A2-A3.
    // frag q: q0=(row g, pair 2tig), q1=(g, 2tig+1), q2=(g+8, 2tig), q3=(g+8, 2tig+1)
    float* outb = head ? g_hs : g_hd;
#pragma unroll
    for (int m = 0; m < 4; m++) {
#pragma unroll
        for (int np = 0; np < 2; np++) {
            const int pxb = warp_n * 32 + np * 16 + tig * 4;
#pragma unroll
            for (int half = 0; half < 2; half++) {   // rows g, g+8
                const int co = cotile * 128 + (warp_m * 4 + m) * 16 + g + half * 8;
                const int q0 = half * 2, q1 = half * 2 + 1;
                float y00 = acc[0][m][np][q0] + acc[1][m][np][q0] + acc[2][m][np][q0];
                float y10 = acc[1][m][np][q0] - acc[2][m][np][q0] - acc[3][m][np][q0];
                float y01 = acc[0][m][np][q1] + acc[1][m][np][q1] + acc[2][m][np][q1];
                float y11 = acc[1][m][np][q1] - acc[2][m][np][q1] - acc[3][m][np][q1];
                float* dst = outb + ((size_t)(n * CH + co)) * HW + row * WW + pxb;
                *(float4*)dst = make_float4(y00, y10, y01, y11);
            }
        }
    }
}

// ============================================================
// Kernel 2a/2b: GroupNorm stats, two-phase.
// ============================================================
__global__ __launch_bounds__(256) void gn_partA_kernel()
{
    const int id = blockIdx.x;               // ((head*8+b)*8+g)*16+slice
    const int head = id >> 10;
    const int b = (id >> 7) & 7;
    const int g = (id >> 4) & 7;
    const int sl = id & 15;
    const float4* p4 = (const float4*)((head ? g_hs : g_hd)
                     + ((size_t)(b * CH + g * CPG)) * HW + sl * 32768);
    const int tid = threadIdx.x;
    float s = 0.f, s2 = 0.f;
    for (int i = tid; i < 8192; i += 256) {
        float4 v = p4[i];
        s += (v.x + v.y) + (v.z + v.w);
        s2 = fmaf(v.x, v.x, fmaf(v.y, v.y, fmaf(v.z, v.z, fmaf(v.w, v.w, s2))));
    }
    __shared__ float sh[256], sh2[256];
    sh[tid] = s; sh2[tid] = s2;
    __syncthreads();
    for (int off = 128; off > 0; off >>= 1) {
        if (tid < off) { sh[tid] += sh[tid + off]; sh2[tid] += sh2[tid + off]; }
        __syncthreads();
    }
    if (tid == 0) { g_part[id * 2] = sh[0]; g_part[id * 2 + 1] = sh2[0]; }
}

__global__ void gn_partB_kernel()
{
    const int t = threadIdx.x;
    if (t >= 128) return;
    float s = 0.f, s2 = 0.f;
    for (int i = 0; i < 16; i++) {
        s  += g_part[(t * 16 + i) * 2];
        s2 += g_part[(t * 16 + i) * 2 + 1];
    }
    const float mu = s / 524288.f;
    const float var = s2 / 524288.f - mu * mu;
    g_stats[t * 2] = mu;
    g_stats[t * 2 + 1] = rsqrtf(var + 1e-5f);
}

// ============================================================
// Kernel 3: per-pixel epilogue. GN affine + exact GELU + 1x1 convs
// + sigmoid/CORN decode/normalize/labels.
// ============================================================
__global__ __launch_bounds__(256) void epilogue_kernel(
    const float* __restrict__ dgs, const float* __restrict__ dgb,
    const float* __restrict__ dw2, const float* __restrict__ db2,
    const float* __restrict__ sgs, const float* __restrict__ sgb,
    const float* __restrict__ sw2, const float* __restrict__ sb2,
    float* __restrict__ out)
{
    __shared__ float s_dgs[CH], s_dgb[CH], s_dw2[CH];
    __shared__ float s_sgs[CH], s_sgb[CH], s_sw0[CH], s_sw1[CH];
    __shared__ float s_mu[2][NGRP], s_rs[2][NGRP];

    const int tid = threadIdx.x;
    const int p   = blockIdx.x * 256 + tid;
    const int n   = p >> 14;
    const int pix = p & 16383;

    for (int c = tid; c < CH; c += 256) {
        s_dgs[c] = dgs[c]; s_dgb[c] = dgb[c]; s_dw2[c] = dw2[c];
        s_sgs[c] = sgs[c]; s_sgb[c] = sgb[c];
        s_sw0[c] = sw2[c]; s_sw1[c] = sw2[CH + c];
    }
    if (tid < 16) {
        int h = tid >> 3, g = tid & 7;
        int idx = ((h * BATCH + n) * NGRP + g) * 2;
        s_mu[h][g] = g_stats[idx];
        s_rs[h][g] = g_stats[idx + 1];
    }
    __syncthreads();

    const float* hd = g_hd + (size_t)n * CH * HW + pix;
    const float* hs = g_hs + (size_t)n * CH * HW + pix;

    float dl = 0.f, sl0 = 0.f, sl1 = 0.f;
#pragma unroll 4
    for (int c = 0; c < CH; c++) {
        const int g = c >> 5;
        float v  = hd[(size_t)c * HW];
        float xn = fmaf((v - s_mu[0][g]) * s_rs[0][g], s_dgs[c], s_dgb[c]);
        float ge = xn * normcdff(xn);
        dl = fmaf(ge, s_dw2[c], dl);

        v  = hs[(size_t)c * HW];
        xn = fmaf((v - s_mu[1][g]) * s_rs[1][g], s_sgs[c], s_sgb[c]);
        ge = xn * normcdff(xn);
        sl0 = fmaf(ge, s_sw0[c], sl0);
        sl1 = fmaf(ge, s_sw1[c], sl1);
    }
    dl  += db2[0];
    sl0 += sb2[0];
    sl1 += sb2[1];

    const float pd = 1.f / (1.f + expf(-dl));
    const float t0 = 1.f / (1.f + expf(-sl0));
    const float t1 = t0 * (1.f / (1.f + expf(-sl1)));
    float sev0 = fmaxf(1.f - t0, 1e-8f);
    float sev1 = fmaxf(t0 - t1, 1e-8f);
    float sev2 = fmaxf(t1,       1e-8f);
    const float ssum = fmaxf(sev0 + sev1 + sev2, 1e-8f);
    sev0 /= ssum; sev1 /= ssum; sev2 /= ssum;

    float px0 = fmaxf(1.f - pd,   1e-8f);
    float px1 = fmaxf(pd * sev0,  1e-8f);
    float px2 = fmaxf(pd * sev1,  1e-8f);
    float px3 = fmaxf(pd * sev2,  1e-8f);
    const float psum = fmaxf(px0 + px1 + px2 + px3, 1e-8f);
    px0 /= psum; px1 /= psum; px2 /= psum; px3 /= psum;

    int sp = 0; float bm = sev0;
    if (sev1 > bm) { bm = sev1; sp = 1; }
    if (sev2 > bm) { bm = sev2; sp = 2; }
    const int lbl = (pd >= 0.5f) ? (sp + 1) : 0;

    out[O_DMG  + n * HW + pix]            = dl;
    out[O_CORN + (n * 2 + 0) * HW + pix]  = sl0;
    out[O_CORN + (n * 2 + 1) * HW + pix]  = sl1;
    out[O_PIX  + (n * 4 + 0) * HW + pix]  = px0;
    out[O_PIX  + (n * 4 + 1) * HW + pix]  = px1;
    out[O_PIX  + (n * 4 + 2) * HW + pix]  = px2;
    out[O_PIX  + (n * 4 + 3) * HW + pix]  = px3;
    out[O_PRED + n * HW + pix]            = (float)lbl;
}

// ============================================================
// Kernel 4: masked mean + exact top-k sum per (b,c). 32 blocks.
// ============================================================
__global__ __launch_bounds__(256) void reduce_topk_kernel(
    const float* __restrict__ mask, const float* __restrict__ pix)
{
    extern __shared__ unsigned skey[];
    __shared__ int   ibuf[256];
    __shared__ float fbuf[256];

    const int tid = threadIdx.x;
    const int b = blockIdx.x >> 2;
    const int c = blockIdx.x & 3;
    const float* pv = pix  + ((size_t)b * 4 + c) * HW;
    const float* mk = mask + (size_t)b * HW;

    for (int i = tid; i < HW; i += 256)
        skey[i] = (mk[i] > 0.5f) ? __float_as_uint(pv[i]) : 0u;
    __syncthreads();

    int   mc = 0;
    float ms = 0.f;
    for (int i = tid; i < HW; i += 256) {
        unsigned kk = skey[i];
        if (kk) { mc++; ms += __uint_as_float(kk); }
    }
    ibuf[tid] = mc; fbuf[tid] = ms;
    __syncthreads();
    for (int off = 128; off > 0; off >>= 1) {
        if (tid < off) { ibuf[tid] += ibuf[tid + off]; fbuf[tid] += fbuf[tid + off]; }
        __syncthreads();
    }
    const int   cnt    = ibuf[0];
    const float sumall = fbuf[0];
    __syncthreads();

    int k = (int)rintf((float)cnt * 0.2f);
    if (k < 1) k = 1;
    const int cmax = (cnt > 1) ? cnt : 1;
    if (k > cmax) k = cmax;

    unsigned prefix = 0u;
    for (int bit = 30; bit >= 0; bit--) {
        const unsigned cand = prefix | (1u << bit);
        int cl = 0;
        for (int i = tid; i < HW; i += 256)
            if (skey[i] >= cand) cl++;
        ibuf[tid] = cl;
        __syncthreads();
        for (int off = 128; off > 0; off >>= 1) {
            if (tid < off) ibuf[tid] += ibuf[tid + off];
            __syncthreads();
        }
        if (ibuf[0] >= k) prefix = cand;
        __syncthreads();
    }

    int   cg = 0;
    float sg = 0.f;
    for (int i = tid; i < HW; i += 256) {
        unsigned kk = skey[i];
        if (kk > prefix) { cg++; sg += __uint_as_float(kk); }
    }
    ibuf[tid] = cg; fbuf[tid] = sg;
    __syncthreads();
    for (int off = 128; off > 0; off >>= 1) {
        if (tid < off) { ibuf[tid] += ibuf[tid + off]; fbuf[tid] += fbuf[tid + off]; }
        __syncthreads();
    }
    if (tid == 0) {
        const float T = __uint_as_float(prefix);
        const float topsum = fbuf[0] + (float)(k - ibuf[0]) * T;
        g_mean_raw[b * 4 + c] = sumall / (float)((cnt > 1) ? cnt : 1);
        g_topk_raw[b * 4 + c] = topsum / (float)k;
        g_cnt[b] = cnt;
    }
}

// ============================================================
// Kernel 5: finalize
// ============================================================
__global__ void finalize_kernel(float* __restrict__ out)
{
    const int b = threadIdx.x;
    if (b >= BATCH) return;
    const int cnt = g_cnt[b];

    float m[4], t[4], a[4];
    float sm = 0.f, st = 0.f;
    for (int c = 0; c < 4; c++) {
        m[c] = (cnt == 0) ? 0.25f : fmaxf(g_mean_raw[b * 4 + c], 1e-8f);
        t[c] = (cnt == 0) ? 0.25f : fmaxf(g_topk_raw[b * 4 + c], 1e-8f);
        sm += m[c]; st += t[c];
    }
    sm = fmaxf(sm, 1e-8f); st = fmaxf(st, 1e-8f);
    float sa = 0.f;
    for (int c = 0; c < 4; c++) {
        m[c] /= sm; t[c] /= st;
        a[c] = fmaxf(0.7f * m[c] + 0.3f * t[c], 1e-8f);
        sa += a[c];
    }
    sa = fmaxf(sa, 1e-8f);
    int best = 0; float bv = -1.f;
    for (int c = 0; c < 4; c++) {
        a[c] /= sa;
        if (a[c] > bv) { bv = a[c]; best = c; }
        out[O_MEAN + b * 4 + c] = m[c];
        out[O_TOPK + b * 4 + c] = t[c];
        out[O_AGG  + b * 4 + c] = a[c];
    }
    out[O_AGGL + b] = (float)best;
}

// ============================================================
extern "C" void kernel_launch(void* const* d_in, const int* in_sizes, int n_in,
                              void* d_out, int out_size)
{
    const float* fm   = (const float*)d_in[0];
    const float* mask = (const float*)d_in[1];
    const float* dw1  = (const float*)d_in[2];
    const float* dgs  = (const float*)d_in[3];
    const float* dgb  = (const float*)d_in[4];
    const float* dw2  = (const float*)d_in[5];
    const float* db2  = (const float*)d_in[6];
    const float* sw1  = (const float*)d_in[7];
    const float* sgs  = (const float*)d_in[8];
    const float* sgb  = (const float*)d_in[9];
    const float* sw2  = (const float*)d_in[10];
    const float* sb2  = (const float*)d_in[11];
    float* out = (float*)d_out;

    cudaFuncSetAttribute(conv_wino_kernel,
                         cudaFuncAttributeMaxDynamicSharedMemorySize, 2 * STAGE_BYTES);
    cudaFuncSetAttribute(convert_in_kernel,
                         cudaFuncAttributeMaxDynamicSharedMemorySize, 128 * TP * 4);
    cudaFuncSetAttribute(reduce_topk_kernel,
                         cudaFuncAttributeMaxDynamicSharedMemorySize, HW * 4);

    convert_w_kernel<<<dim3(32, 12, 2), 256>>>(dw1, sw1);
    convert_in_kernel<<<dim3(2, 128, 8), 256, 128 * TP * 4>>>(fm);
    conv_wino_kernel<<<dim3(4, 1024), 256, 2 * STAGE_BYTES>>>();
    gn_partA_kernel<<<2048, 256>>>();
    gn_partB_kernel<<<1, 128>>>();
    epilogue_kernel<<<NPIX / 256, 256>>>(dgs, dgb, dw2, db2, sgs, sgb, sw2, sb2, out);
    reduce_topk_kernel<<<BATCH * 4, 256, HW * 4>>>(mask, out + O_PIX);
    finalize_kernel<<<1, 32>>>(out);
}

// round 14
// speedup vs baseline: 1.8400x; 1.0583x over previous
#include <cuda_runtime.h>
#include <cuda_fp16.h>
#include <math.h>
#include <stdint.h>

// Problem constants
#define BATCH 8
#define CIN   256
#define CH    256
#define HH    128
#define WW    128
#define HW    (HH*WW)          // 16384
#define NPIX  (BATCH*HW)       // 131072
#define NGRP  8
#define CPG   32

// Output layout (float32, tuple order, flattened+concatenated)
#define O_DMG   0
#define O_CORN  131072
#define O_PIX   393216
#define O_PRED  917504
#define O_MEAN  1048576
#define O_TOPK  1048608
#define O_AGG   1048640
#define O_AGGL  1048672

// -------- scratch (no cudaMalloc allowed) --------
__device__ float g_hd[(size_t)BATCH*CH*HW];          // damage conv3x3 out
__device__ float g_hs[(size_t)BATCH*CH*HW];          // severity conv3x3 out
// Winograd weights, fp16 frag-permuted:
// plane = (head*4+comp)*3 + r ; [plane][mg(16)][kk(16)][lane(32)] uint4
__device__ uint4 g_wah[2*4*3*16*16*32];
__device__ uint4 g_wal[2*4*3*16*16*32];
// Winograd input components, fp16 frag-permuted:
// [(comp*BATCH+n)][pg(1024)][kk(16)][lane(32)] uint2  (pair-group of 8 pairs)
__device__ __align__(16) uint2 g_bh[(size_t)4*BATCH*1024*16*32];
__device__ __align__(16) uint2 g_bl[(size_t)4*BATCH*1024*16*32];
__device__ float g_part[2048*2];
__device__ float g_stats[2*BATCH*NGRP*2];
__device__ float g_mean_raw[BATCH*4];
__device__ float g_topk_raw[BATCH*4];
__device__ int   g_cnt[BATCH];

#define MMA_FP16(c, a, b0, b1) \
    asm volatile("mma.sync.aligned.m16n8k16.row.col.f32.f16.f16.f32 " \
        "{%0,%1,%2,%3},{%4,%5,%6,%7},{%8,%9},{%0,%1,%2,%3};" \
        : "+f"((c)[0]), "+f"((c)[1]), "+f"((c)[2]), "+f"((c)[3]) \
        : "r"((a).x), "r"((a).y), "r"((a).z), "r"((a).w), "r"(b0), "r"(b1))

#define CP_ASYNC16(dst, src) \
    asm volatile("cp.async.cg.shared.global [%0], [%1], 16;" :: "r"(dst), "l"(src) : "memory")
#define CP_ASYNC16P(dst, src, sz) \
    asm volatile("cp.async.cg.shared.global [%0], [%1], 16, %2;" :: "r"(dst), "l"(src), "r"(sz) : "memory")
#define CP_COMMIT()  asm volatile("cp.async.commit_group;" ::: "memory")
#define CP_WAIT1()   asm volatile("cp.async.wait_group 1;" ::: "memory")

__device__ __forceinline__ uint32_t pack_h2(float a, float b) {
    __half2 h = __halves2half2(__float2half_rn(a), __float2half_rn(b));
    return *reinterpret_cast<uint32_t*>(&h);
}

// ============================================================
// Kernel 0a: Winograd weight transform + fp16 hi/lo split,
// m16n8k16 frag-permuted. grid = (32, 12, 2) [y = comp*3+r].
// G0=g0, G1=(g0+g1+g2)/2, G2=(g0-g1+g2)/2, G3=g2.
// ============================================================
__global__ __launch_bounds__(256) void convert_w_kernel(
    const float* __restrict__ dw1, const float* __restrict__ sw1)
{
    const int i = blockIdx.x * 256 + threadIdx.x;    // 0..8191
    const int mg = i >> 9;
    const int kk = (i >> 5) & 15;
    const int l  = i & 31;
    const int g = l >> 2, tig = l & 3;
    const int head = blockIdx.z;
    const int comp = blockIdx.y / 3, r = blockIdx.y - comp * 3;
    const float* w = head ? sw1 : dw1;

    const int co0 = mg * 16 + g;
    const int ciA = kk * 16 + 2 * tig;
    const int ciB = ciA + 8;

    const int cos[8]  = {co0, co0, co0 + 8, co0 + 8, co0, co0, co0 + 8, co0 + 8};
    const int cis[8]  = {ciA, ciA + 1, ciA, ciA + 1, ciB, ciB + 1, ciB, ciB + 1};

    float v[8];
#pragma unroll
    for (int q = 0; q < 8; q++) {
        const float* wp = w + ((size_t)(cos[q] * CIN + cis[q]) * 3 + r) * 3;
        float w0 = wp[0], w1 = wp[1], w2 = wp[2];
        float G;
        if      (comp == 0) G = w0;
        else if (comp == 1) G = 0.5f * (w0 + w1 + w2);
        else if (comp == 2) G = 0.5f * (w0 - w1 + w2);
        else                G = w2;
        v[q] = G;
    }
    float h[8], lo[8];
#pragma unroll
    for (int q = 0; q < 8; q++) {
        h[q]  = __half2float(__float2half_rn(v[q]));
        lo[q] = v[q] - h[q];
    }
    uint4 hi4, lo4;
    hi4.x = pack_h2(h[0], h[1]);  lo4.x = pack_h2(lo[0], lo[1]);
    hi4.y = pack_h2(h[2], h[3]);  lo4.y = pack_h2(lo[2], lo[3]);
    hi4.z = pack_h2(h[4], h[5]);  lo4.z = pack_h2(lo[4], lo[5]);
    hi4.w = pack_h2(h[6], h[7]);  lo4.w = pack_h2(lo[6], lo[7]);
    const size_t off = (((size_t)((head * 4 + comp) * 3 + r) * 16 + mg) * 16 + kk) * 32 + l;
    g_wah[off] = hi4;
    g_wal[off] = lo4;
}

// ============================================================
// Kernel 0b: input -> Winograd components c0..c3 per x-pair,
// fp16 hi/lo split, frag-permuted. Block = (ci-half, y-row).
// grid = (2, 128, 8), 256 thr. c0=d0-d2, c1=d1+d2, c2=d2-d1,
// c3=d1-d3 with d = in at x = 2t-1..2t+2 (zero pad at edges).
// ============================================================
#define TP 132
__global__ __launch_bounds__(256) void convert_in_kernel(const float* __restrict__ in)
{
    extern __shared__ float tile[];   // [128][TP]
    const int cihalf = blockIdx.x, y = blockIdx.y, n = blockIdx.z;
    const int ci0 = cihalf * 128;
    const int tid = threadIdx.x;

    // load 128 ci x 128 x, coalesced
    {
        const int c = tid >> 1, xs = (tid & 1) * 64;
        const float* src = in + ((size_t)(n * CIN + ci0 + c)) * HW + y * WW + xs;
        float* drow = tile + c * TP + xs;
        const float4* s4 = (const float4*)src;
#pragma unroll
        for (int j = 0; j < 16; j++)
            *(float4*)(drow + j * 4) = s4[j];
    }
    __syncthreads();

    const int kk_rel = tid >> 5;      // 0..7
    const int l = tid & 31;
    const int g = l >> 2, tig = l & 3;
    const int kk = cihalf * 8 + kk_rel;
    const int cb = kk_rel * 16 + 2 * tig;
    const int cs[4] = {cb, cb + 1, cb + 8, cb + 9};

#pragma unroll
    for (int pg_rel = 0; pg_rel < 8; pg_rel++) {
        const int t = pg_rel * 8 + g;        // pair index within row, 0..63
        const int x0 = 2 * t;
        float comp_v[4][4];                  // [comp][ci-slot]
#pragma unroll
        for (int q = 0; q < 4; q++) {
            const float* row = tile + cs[q] * TP;
            float d0 = (t > 0)  ? row[x0 - 1] : 0.f;
            float d1 = row[x0];
            float d2 = row[x0 + 1];
            float d3 = (t < 63) ? row[x0 + 2] : 0.f;
            comp_v[0][q] = d0 - d2;
            comp_v[1][q] = d1 + d2;
            comp_v[2][q] = d2 - d1;
            comp_v[3][q] = d1 - d3;
        }
        const int pg = y * 8 + pg_rel;
#pragma unroll
        for (int comp = 0; comp < 4; comp++) {
            float h[4], lo[4];
#pragma unroll
            for (int q = 0; q < 4; q++) {
                h[q]  = __half2float(__float2half_rn(comp_v[comp][q]));
                lo[q] = comp_v[comp][q] - h[q];
            }
            uint2 hi2, lo2;
            hi2.x = pack_h2(h[0], h[1]);  lo2.x = pack_h2(lo[0], lo[1]);
            hi2.y = pack_h2(h[2], h[3]);  lo2.y = pack_h2(lo[2], lo[3]);
            const size_t off = (((size_t)(comp * BATCH + n) * 1024 + pg) * 16 + kk) * 32 + l;
            g_bh[off] = hi2;
            g_bl[off] = lo2;
        }
    }
}

// ============================================================
// Kernel 1: conv3x3 via 1D-Winograd F(2,3) + 3-term fp16-split
// m16n8k16 GEMMs. CTA = 128co x 64 pairs (one y-row), 8 warps
// (2m x 4n) of 64co x 16 pairs. 24 stages of K=128
// (comp(4) x r(3) x kk-half(2)), 2-stage cp.async, 96KB/stage
// (192KB total -> 1 CTA/SM, the proven high-efficiency regime).
// grid = dim3(4, 1024).
// ============================================================
#define STAGE_BYTES 98304   // Ah 32K | Al 32K | Bh 16K | Bl 16K
#define A_LO_OFF 32768
#define B_HI_OFF 65536
#define B_LO_OFF 81920

__device__ __forceinline__ void stage_load(
    char* sp, int cn, int t6, int head, int cotile, int n, int pg0, int tid)
{
    const int r   = t6 >> 1;
    const int kk0 = (t6 & 1) * 8;

    // A: 4096 uint4 (hi 2048 + lo 2048), 16 per thread
    const size_t abase = ((size_t)((head * 4 + cn) * 3 + r) * 16 + cotile * 8) * 512;
#pragma unroll
    for (int it = 0; it < 16; it++) {
        const int cid = tid + it * 256;
        const int prec = cid >> 11, cc = cid & 2047;
        const int mgl = cc >> 8, kkl = (cc >> 5) & 7, ll = cc & 31;
        const uint4* src = (prec ? g_wal : g_wah) + abase + mgl * 512 + (kk0 + kkl) * 32 + ll;
        uint32_t dst = (uint32_t)__cvta_generic_to_shared(
            sp + prec * A_LO_OFF + ((mgl * 8 + kkl) * 32 + ll) * 16);
        CP_ASYNC16(dst, src);
    }
    // B: 2048 x 16B chunks (lane-paired uint2s, hi+lo), 8 per thread
    const size_t bbase = (size_t)(cn * BATCH + n) * 1024;
    const int pgsh = pg0 + (r - 1) * 8;
#pragma unroll
    for (int it = 0; it < 8; it++) {
        const int cid = tid + it * 256;
        const int prec = cid >> 10, cc = cid & 1023;
        const int kkl = cc >> 7, pgl = (cc >> 4) & 7, ll2 = cc & 15;
        const int pgsrc = pgsh + pgl;
        const unsigned ok = ((unsigned)pgsrc < 1024u);
        const int pgc = ok ? pgsrc : 0;
        const uint2* src = (prec ? g_bl : g_bh)
            + ((bbase + pgc) * 16 + kk0 + kkl) * 32 + ll2 * 2;
        uint32_t dst = (uint32_t)__cvta_generic_to_shared(
            sp + B_HI_OFF + prec * 16384 + ((kkl * 8 + pgl) * 32 + ll2 * 2) * 8);
        CP_ASYNC16P(dst, src, ok ? 16u : 0u);
    }
}

__global__ __launch_bounds__(256, 1) void conv_wino_kernel()
{
    extern __shared__ char smem[];
    const int tid = threadIdx.x;
    const int lane = tid & 31;
    const int wid = tid >> 5;
    const int warp_m = wid >> 2;       // 0..1 -> 64 co
    const int warp_n = wid & 3;        // 0..3 -> 16 pairs
    const int g = lane >> 2, tig = lane & 3;

    const int head   = blockIdx.x >> 1;
    const int cotile = blockIdx.x & 1;
    const int ptile  = blockIdx.y;     // 0..1023
    const int n      = ptile >> 7;     // image
    const int row    = ptile & 127;    // y
    const int pg0    = row * 8;        // pair-group base (8 pg per row)

    float acc[4][4][2][4];             // [comp][m][np][q]
#pragma unroll
    for (int c4 = 0; c4 < 4; c4++)
#pragma unroll
        for (int m = 0; m < 4; m++)
#pragma unroll
            for (int np = 0; np < 2; np++)
#pragma unroll
                for (int q = 0; q < 4; q++) acc[c4][m][np][q] = 0.f;

    char* buf0 = smem;
    char* buf1 = smem + STAGE_BYTES;

    stage_load(buf0, 0, 0, head, cotile, n, pg0, tid); CP_COMMIT();
    stage_load(buf1, 0, 1, head, cotile, n, pg0, tid); CP_COMMIT();

#pragma unroll
    for (int comp = 0; comp < 4; comp++) {
        for (int t = 0; t < 6; t++) {
            const int sidx = comp * 6 + t;
            CP_WAIT1();
            __syncthreads();
            char* sp = (sidx & 1) ? buf1 : buf0;

#pragma unroll
            for (int kkl = 0; kkl < 8; kkl++) {
                uint4 Ah[4], Al[4];
#pragma unroll
                for (int m = 0; m < 4; m++) {
                    const int mgl = warp_m * 4 + m;
                    Ah[m] = *(const uint4*)(sp + ((mgl * 8 + kkl) * 32 + lane) * 16);
                    Al[m] = *(const uint4*)(sp + A_LO_OFF + ((mgl * 8 + kkl) * 32 + lane) * 16);
                }
#pragma unroll
                for (int np = 0; np < 2; np++) {
                    const int pgl = warp_n * 2 + np;
                    uint2 bh = *(const uint2*)(sp + B_HI_OFF + ((kkl * 8 + pgl) * 32 + lane) * 8);
                    uint2 bl = *(const uint2*)(sp + B_LO_OFF + ((kkl * 8 + pgl) * 32 + lane) * 8);
#pragma unroll
                    for (int m = 0; m < 4; m++) {
                        MMA_FP16(acc[comp][m][np], Ah[m], bh.x, bh.y);
                        MMA_FP16(acc[comp][m][np], Al[m], bh.x, bh.y);
                        MMA_FP16(acc[comp][m][np], Ah[m], bl.x, bl.y);
                    }
                }
            }
            __syncthreads();
            if (sidx + 2 < 24) {
                int tn = t + 2, cn = comp;
                if (tn >= 6) { tn -= 6; cn += 1; }
                stage_load((sidx & 1) ? buf1 : buf0, cn, tn, head, cotile, n, pg0, tid);
            }
            CP_COMMIT();
        }
    }

    // Winograd recombine + store: y0 = A0+A1+A2, y1 = A1-A2-A3.
    // frag q: q0=(row g, pair 2tig), q1=(g, 2tig+1), q2=(g+8, 2tig), q3=(g+8, 2tig+1)
    float* outb = head ? g_hs : g_hd;
#pragma unroll
    for (int m = 0; m < 4; m++) {
#pragma unroll
        for (int np = 0; np < 2; np++) {
            const int pxb = warp_n * 32 + np * 16 + tig * 4;
#pragma unroll
            for (int half = 0; half < 2; half++) {   // rows g, g+8
                const int co = cotile * 128 + (warp_m * 4 + m) * 16 + g + half * 8;
                const int q0 = half * 2, q1 = half * 2 + 1;
                float y00 = acc[0][m][np][q0] + acc[1][m][np][q0] + acc[2][m][np][q0];
                float y10 = acc[1][m][np][q0] - acc[2][m][np][q0] - acc[3][m][np][q0];
                float y01 = acc[0][m][np][q1] + acc[1][m][np][q1] + acc[2][m][np][q1];
                float y11 = acc[1][m][np][q1] - acc[2][m][np][q1] - acc[3][m][np][q1];
                float* dst = outb + ((size_t)(n * CH + co)) * HW + row * WW + pxb;
                *(float4*)dst = make_float4(y00, y10, y01, y11);
            }
        }
    }
}

// ============================================================
// Kernel 2a/2b: GroupNorm stats, two-phase.
// ============================================================
__global__ __launch_bounds__(256) void gn_partA_kernel()
{
    const int id = blockIdx.x;               // ((head*8+b)*8+g)*16+slice
    const int head = id >> 10;
    const int b = (id >> 7) & 7;
    const int g = (id >> 4) & 7;
    const int sl = id & 15;
    const float4* p4 = (const float4*)((head ? g_hs : g_hd)
                     + ((size_t)(b * CH + g * CPG)) * HW + sl * 32768);
    const int tid = threadIdx.x;
    float s = 0.f, s2 = 0.f;
    for (int i = tid; i < 8192; i += 256) {
        float4 v = p4[i];
        s += (v.x + v.y) + (v.z + v.w);
        s2 = fmaf(v.x, v.x, fmaf(v.y, v.y, fmaf(v.z, v.z, fmaf(v.w, v.w, s2))));
    }
    __shared__ float sh[256], sh2[256];
    sh[tid] = s; sh2[tid] = s2;
    __syncthreads();
    for (int off = 128; off > 0; off >>= 1) {
        if (tid < off) { sh[tid] += sh[tid + off]; sh2[tid] += sh2[tid + off]; }
        __syncthreads();
    }
    if (tid == 0) { g_part[id * 2] = sh[0]; g_part[id * 2 + 1] = sh2[0]; }
}

__global__ void gn_partB_kernel()
{
    const int t = threadIdx.x;
    if (t >= 128) return;
    float s = 0.f, s2 = 0.f;
    for (int i = 0; i < 16; i++) {
        s  += g_part[(t * 16 + i) * 2];
        s2 += g_part[(t * 16 + i) * 2 + 1];
    }
    const float mu = s / 524288.f;
    const float var = s2 / 524288.f - mu * mu;
    g_stats[t * 2] = mu;
    g_stats[t * 2 + 1] = rsqrtf(var + 1e-5f);
}

// ============================================================
// Kernel 3: per-pixel epilogue. GN affine + exact GELU + 1x1 convs
// + sigmoid/CORN decode/normalize/labels.
// ============================================================
__global__ __launch_bounds__(256) void epilogue_kernel(
    const float* __restrict__ dgs, const float* __restrict__ dgb,
    const float* __restrict__ dw2, const float* __restrict__ db2,
    const float* __restrict__ sgs, const float* __restrict__ sgb,
    const float* __restrict__ sw2, const float* __restrict__ sb2,
    float* __restrict__ out)
{
    __shared__ float s_dgs[CH], s_dgb[CH], s_dw2[CH];
    __shared__ float s_sgs[CH], s_sgb[CH], s_sw0[CH], s_sw1[CH];
    __shared__ float s_mu[2][NGRP], s_rs[2][NGRP];

    const int tid = threadIdx.x;
    const int p   = blockIdx.x * 256 + tid;
    const int n   = p >> 14;
    const int pix = p & 16383;

    for (int c = tid; c < CH; c += 256) {
        s_dgs[c] = dgs[c]; s_dgb[c] = dgb[c]; s_dw2[c] = dw2[c];
        s_sgs[c] = sgs[c]; s_sgb[c] = sgb[c];
        s_sw0[c] = sw2[c]; s_sw1[c] = sw2[CH + c];
    }
    if (tid < 16) {
        int h = tid >> 3, g = tid & 7;
        int idx = ((h * BATCH + n) * NGRP + g) * 2;
        s_mu[h][g] = g_stats[idx];
        s_rs[h][g] = g_stats[idx + 1];
    }
    __syncthreads();

    const float* hd = g_hd + (size_t)n * CH * HW + pix;
    const float* hs = g_hs + (size_t)n * CH * HW + pix;

    float dl = 0.f, sl0 = 0.f, sl1 = 0.f;
#pragma unroll 4
    for (int c = 0; c < CH; c++) {
        const int g = c >> 5;
        float v  = hd[(size_t)c * HW];
        float xn = fmaf((v - s_mu[0][g]) * s_rs[0][g], s_dgs[c], s_dgb[c]);
        float ge = xn * normcdff(xn);
        dl = fmaf(ge, s_dw2[c], dl);

        v  = hs[(size_t)c * HW];
        xn = fmaf((v - s_mu[1][g]) * s_rs[1][g], s_sgs[c], s_sgb[c]);
        ge = xn * normcdff(xn);
        sl0 = fmaf(ge, s_sw0[c], sl0);
        sl1 = fmaf(ge, s_sw1[c], sl1);
    }
    dl  += db2[0];
    sl0 += sb2[0];
    sl1 += sb2[1];

    const float pd = 1.f / (1.f + expf(-dl));
    const float t0 = 1.f / (1.f + expf(-sl0));
    const float t1 = t0 * (1.f / (1.f + expf(-sl1)));
    float sev0 = fmaxf(1.f - t0, 1e-8f);
    float sev1 = fmaxf(t0 - t1, 1e-8f);
    float sev2 = fmaxf(t1,       1e-8f);
    const float ssum = fmaxf(sev0 + sev1 + sev2, 1e-8f);
    sev0 /= ssum; sev1 /= ssum; sev2 /= ssum;

    float px0 = fmaxf(1.f - pd,   1e-8f);
    float px1 = fmaxf(pd * sev0,  1e-8f);
    float px2 = fmaxf(pd * sev1,  1e-8f);
    float px3 = fmaxf(pd * sev2,  1e-8f);
    const float psum = fmaxf(px0 + px1 + px2 + px3, 1e-8f);
    px0 /= psum; px1 /= psum; px2 /= psum; px3 /= psum;

    int sp = 0; float bm = sev0;
    if (sev1 > bm) { bm = sev1; sp = 1; }
    if (sev2 > bm) { bm = sev2; sp = 2; }
    const int lbl = (pd >= 0.5f) ? (sp + 1) : 0;

    out[O_DMG  + n * HW + pix]            = dl;
    out[O_CORN + (n * 2 + 0) * HW + pix]  = sl0;
    out[O_CORN + (n * 2 + 1) * HW + pix]  = sl1;
    out[O_PIX  + (n * 4 + 0) * HW + pix]  = px0;
    out[O_PIX  + (n * 4 + 1) * HW + pix]  = px1;
    out[O_PIX  + (n * 4 + 2) * HW + pix]  = px2;
    out[O_PIX  + (n * 4 + 3) * HW + pix]  = px3;
    out[O_PRED + n * HW + pix]            = (float)lbl;
}

// ============================================================
// Kernel 4: masked mean + exact top-k sum per (b,c). 32 blocks.
// ============================================================
__global__ __launch_bounds__(256) void reduce_topk_kernel(
    const float* __restrict__ mask, const float* __restrict__ pix)
{
    extern __shared__ unsigned skey[];
    __shared__ int   ibuf[256];
    __shared__ float fbuf[256];

    const int tid = threadIdx.x;
    const int b = blockIdx.x >> 2;
    const int c = blockIdx.x & 3;
    const float* pv = pix  + ((size_t)b * 4 + c) * HW;
    const float* mk = mask + (size_t)b * HW;

    for (int i = tid; i < HW; i += 256)
        skey[i] = (mk[i] > 0.5f) ? __float_as_uint(pv[i]) : 0u;
    __syncthreads();

    int   mc = 0;
    float ms = 0.f;
    for (int i = tid; i < HW; i += 256) {
        unsigned kk = skey[i];
        if (kk) { mc++; ms += __uint_as_float(kk); }
    }
    ibuf[tid] = mc; fbuf[tid] = ms;
    __syncthreads();
    for (int off = 128; off > 0; off >>= 1) {
        if (tid < off) { ibuf[tid] += ibuf[tid + off]; fbuf[tid] += fbuf[tid + off]; }
        __syncthreads();
    }
    const int   cnt    = ibuf[0];
    const float sumall = fbuf[0];
    __syncthreads();

    int k = (int)rintf((float)cnt * 0.2f);
    if (k < 1) k = 1;
    const int cmax = (cnt > 1) ? cnt : 1;
    if (k > cmax) k = cmax;

    unsigned prefix = 0u;
    for (int bit = 30; bit >= 0; bit--) {
        const unsigned cand = prefix | (1u << bit);
        int cl = 0;
        for (int i = tid; i < HW; i += 256)
            if (skey[i] >= cand) cl++;
        ibuf[tid] = cl;
        __syncthreads();
        for (int off = 128; off > 0; off >>= 1) {
            if (tid < off) ibuf[tid] += ibuf[tid + off];
            __syncthreads();
        }
        if (ibuf[0] >= k) prefix = cand;
        __syncthreads();
    }

    int   cg = 0;
    float sg = 0.f;
    for (int i = tid; i < HW; i += 256) {
        unsigned kk = skey[i];
        if (kk > prefix) { cg++; sg += __uint_as_float(kk); }
    }
    ibuf[tid] = cg; fbuf[tid] = sg;
    __syncthreads();
    for (int off = 128; off > 0; off >>= 1) {
        if (tid < off) { ibuf[tid] += ibuf[tid + off]; fbuf[tid] += fbuf[tid + off]; }
        __syncthreads();
    }
    if (tid == 0) {
        const float T = __uint_as_float(prefix);
        const float topsum = fbuf[0] + (float)(k - ibuf[0]) * T;
        g_mean_raw[b * 4 + c] = sumall / (float)((cnt > 1) ? cnt : 1);
        g_topk_raw[b * 4 + c] = topsum / (float)k;
        g_cnt[b] = cnt;
    }
}

// ============================================================
// Kernel 5: finalize
// ============================================================
__global__ void finalize_kernel(float* __restrict__ out)
{
    const int b = threadIdx.x;
    if (b >= BATCH) return;
    const int cnt = g_cnt[b];

    float m[4], t[4], a[4];
    float sm = 0.f, st = 0.f;
    for (int c = 0; c < 4; c++) {
        m[c] = (cnt == 0) ? 0.25f : fmaxf(g_mean_raw[b * 4 + c], 1e-8f);
        t[c] = (cnt == 0) ? 0.25f : fmaxf(g_topk_raw[b * 4 + c], 1e-8f);
        sm += m[c]; st += t[c];
    }
    sm = fmaxf(sm, 1e-8f); st = fmaxf(st, 1e-8f);
    float sa = 0.f;
    for (int c = 0; c < 4; c++) {
        m[c] /= sm; t[c] /= st;
        a[c] = fmaxf(0.7f * m[c] + 0.3f * t[c], 1e-8f);
        sa += a[c];
    }
    sa = fmaxf(sa, 1e-8f);
    int best = 0; float bv = -1.f;
    for (int c = 0; c < 4; c++) {
        a[c] /= sa;
        if (a[c] > bv) { bv = a[c]; best = c; }
        out[O_MEAN + b * 4 + c] = m[c];
        out[O_TOPK + b * 4 + c] = t[c];
        out[O_AGG  + b * 4 + c] = a[c];
    }
    out[O_AGGL + b] = (float)best;
}

// ============================================================
extern "C" void kernel_launch(void* const* d_in, const int* in_sizes, int n_in,
                              void* d_out, int out_size)
{
    const float* fm   = (const float*)d_in[0];
    const float* mask = (const float*)d_in[1];
    const float* dw1  = (const float*)d_in[2];
    const float* dgs  = (const float*)d_in[3];
    const float* dgb  = (const float*)d_in[4];
    const float* dw2  = (const float*)d_in[5];
    const float* db2  = (const float*)d_in[6];
    const float* sw1  = (const float*)d_in[7];
    const float* sgs  = (const float*)d_in[8];
    const float* sgb  = (const float*)d_in[9];
    const float* sw2  = (const float*)d_in[10];
    const float* sb2  = (const float*)d_in[11];
    float* out = (float*)d_out;

    cudaFuncSetAttribute(conv_wino_kernel,
                         cudaFuncAttributeMaxDynamicSharedMemorySize, 2 * STAGE_BYTES);
    cudaFuncSetAttribute(convert_in_kernel,
                         cudaFuncAttributeMaxDynamicSharedMemorySize, 128 * TP * 4);
    cudaFuncSetAttribute(reduce_topk_kernel,
                         cudaFuncAttributeMaxDynamicSharedMemorySize, HW * 4);

    convert_w_kernel<<<dim3(32, 12, 2), 256>>>(dw1, sw1);
    convert_in_kernel<<<dim3(2, 128, 8), 256, 128 * TP * 4>>>(fm);
    conv_wino_kernel<<<dim3(4, 1024), 256, 2 * STAGE_BYTES>>>();
    gn_partA_kernel<<<2048, 256>>>();
    gn_partB_kernel<<<1, 128>>>();
    epilogue_kernel<<<NPIX / 256, 256>>>(dgs, dgb, dw2, db2, sgs, sgb, sw2, sb2, out);
    reduce_topk_kernel<<<BATCH * 4, 256, HW * 4>>>(mask, out + O_PIX);
    finalize_kernel<<<1, 32>>>(out);
}

// round 16
// speedup vs baseline: 1.9432x; 1.0561x over previous
#include <cuda_runtime.h>
#include <cuda_fp16.h>
#include <math.h>
#include <stdint.h>

// Problem constants
#define BATCH 8
#define CIN   256
#define CH    256
#define HH    128
#define WW    128
#define HW    (HH*WW)          // 16384
#define NPIX  (BATCH*HW)       // 131072
#define NGRP  8
#define CPG   32

// Output layout (float32, tuple order, flattened+concatenated)
#define O_DMG   0
#define O_CORN  131072
#define O_PIX   393216
#define O_PRED  917504
#define O_MEAN  1048576
#define O_TOPK  1048608
#define O_AGG   1048640
#define O_AGGL  1048672

// -------- scratch (no cudaMalloc allowed) --------
__device__ float g_hd[(size_t)BATCH*CH*HW];          // damage conv3x3 out
__device__ float g_hs[(size_t)BATCH*CH*HW];          // severity conv3x3 out
// Winograd weights, fp16 frag-permuted:
// plane = (head*4+comp)*3 + r ; [plane][mg(16)][kk(16)][lane(32)] uint4
__device__ uint4 g_wah[2*4*3*16*16*32];
__device__ uint4 g_wal[2*4*3*16*16*32];
// Winograd input components, fp16 frag-permuted:
// [(comp*BATCH+n)][pg(1024)][kk(16)][lane(32)] uint2  (pair-group of 8 pairs)
__device__ __align__(16) uint2 g_bh[(size_t)4*BATCH*1024*16*32];
__device__ __align__(16) uint2 g_bl[(size_t)4*BATCH*1024*16*32];
__device__ float g_part[2048*2];
__device__ float g_stats[2*BATCH*NGRP*2];
__device__ float g_mean_raw[BATCH*4];
__device__ float g_topk_raw[BATCH*4];
__device__ int   g_cnt[BATCH];

#define MMA_FP16(c, a, b0, b1) \
    asm volatile("mma.sync.aligned.m16n8k16.row.col.f32.f16.f16.f32 " \
        "{%0,%1,%2,%3},{%4,%5,%6,%7},{%8,%9},{%0,%1,%2,%3};" \
        : "+f"((c)[0]), "+f"((c)[1]), "+f"((c)[2]), "+f"((c)[3]) \
        : "r"((a).x), "r"((a).y), "r"((a).z), "r"((a).w), "r"(b0), "r"(b1))

#define CP_ASYNC16(dst, src) \
    asm volatile("cp.async.cg.shared.global [%0], [%1], 16;" :: "r"(dst), "l"(src) : "memory")
#define CP_ASYNC16P(dst, src, sz) \
    asm volatile("cp.async.cg.shared.global [%0], [%1], 16, %2;" :: "r"(dst), "l"(src), "r"(sz) : "memory")
#define CP_COMMIT()  asm volatile("cp.async.commit_group;" ::: "memory")
#define CP_WAIT1()   asm volatile("cp.async.wait_group 1;" ::: "memory")

__device__ __forceinline__ uint32_t pack_h2(float a, float b) {
    __half2 h = __halves2half2(__float2half_rn(a), __float2half_rn(b));
    return *reinterpret_cast<uint32_t*>(&h);
}

// ============================================================
// Kernel 0a: Winograd weight transform + fp16 hi/lo split,
// m16n8k16 frag-permuted. grid = (32, 12, 2) [y = comp*3+r].
// G0=g0, G1=(g0+g1+g2)/2, G2=(g0-g1+g2)/2, G3=g2.
// ============================================================
__global__ __launch_bounds__(256) void convert_w_kernel(
    const float* __restrict__ dw1, const float* __restrict__ sw1)
{
    const int i = blockIdx.x * 256 + threadIdx.x;    // 0..8191
    const int mg = i >> 9;
    const int kk = (i >> 5) & 15;
    const int l  = i & 31;
    const int g = l >> 2, tig = l & 3;
    const int head = blockIdx.z;
    const int comp = blockIdx.y / 3, r = blockIdx.y - comp * 3;
    const float* w = head ? sw1 : dw1;

    const int co0 = mg * 16 + g;
    const int ciA = kk * 16 + 2 * tig;
    const int ciB = ciA + 8;

    const int cos[8]  = {co0, co0, co0 + 8, co0 + 8, co0, co0, co0 + 8, co0 + 8};
    const int cis[8]  = {ciA, ciA + 1, ciA, ciA + 1, ciB, ciB + 1, ciB, ciB + 1};

    float v[8];
#pragma unroll
    for (int q = 0; q < 8; q++) {
        const float* wp = w + ((size_t)(cos[q] * CIN + cis[q]) * 3 + r) * 3;
        float w0 = wp[0], w1 = wp[1], w2 = wp[2];
        float G;
        if      (comp == 0) G = w0;
        else if (comp == 1) G = 0.5f * (w0 + w1 + w2);
        else if (comp == 2) G = 0.5f * (w0 - w1 + w2);
        else                G = w2;
        v[q] = G;
    }
    float h[8], lo[8];
#pragma unroll
    for (int q = 0; q < 8; q++) {
        h[q]  = __half2float(__float2half_rn(v[q]));
        lo[q] = v[q] - h[q];
    }
    uint4 hi4, lo4;
    hi4.x = pack_h2(h[0], h[1]);  lo4.x = pack_h2(lo[0], lo[1]);
    hi4.y = pack_h2(h[2], h[3]);  lo4.y = pack_h2(lo[2], lo[3]);
    hi4.z = pack_h2(h[4], h[5]);  lo4.z = pack_h2(lo[4], lo[5]);
    hi4.w = pack_h2(h[6], h[7]);  lo4.w = pack_h2(lo[6], lo[7]);
    const size_t off = (((size_t)((head * 4 + comp) * 3 + r) * 16 + mg) * 16 + kk) * 32 + l;
    g_wah[off] = hi4;
    g_wal[off] = lo4;
}

// ============================================================
// Kernel 0b: input -> Winograd components c0..c3 per x-pair,
// fp16 hi/lo split, frag-permuted. Block = (ci-half, y-row).
// grid = (2, 128, 8), 256 thr. c0=d0-d2, c1=d1+d2, c2=d2-d1,
// c3=d1-d3 with d = in at x = 2t-1..2t+2 (zero pad at edges).
// ============================================================
#define TP 132
__global__ __launch_bounds__(256) void convert_in_kernel(const float* __restrict__ in)
{
    extern __shared__ float tile[];   // [128][TP]
    const int cihalf = blockIdx.x, y = blockIdx.y, n = blockIdx.z;
    const int ci0 = cihalf * 128;
    const int tid = threadIdx.x;

    // load 128 ci x 128 x, coalesced
    {
        const int c = tid >> 1, xs = (tid & 1) * 64;
        const float* src = in + ((size_t)(n * CIN + ci0 + c)) * HW + y * WW + xs;
        float* drow = tile + c * TP + xs;
        const float4* s4 = (const float4*)src;
#pragma unroll
        for (int j = 0; j < 16; j++)
            *(float4*)(drow + j * 4) = s4[j];
    }
    __syncthreads();

    const int kk_rel = tid >> 5;      // 0..7
    const int l = tid & 31;
    const int g = l >> 2, tig = l & 3;
    const int kk = cihalf * 8 + kk_rel;
    const int cb = kk_rel * 16 + 2 * tig;
    const int cs[4] = {cb, cb + 1, cb + 8, cb + 9};

#pragma unroll
    for (int pg_rel = 0; pg_rel < 8; pg_rel++) {
        const int t = pg_rel * 8 + g;        // pair index within row, 0..63
        const int x0 = 2 * t;
        float comp_v[4][4];                  // [comp][ci-slot]
#pragma unroll
        for (int q = 0; q < 4; q++) {
            const float* row = tile + cs[q] * TP;
            float d0 = (t > 0)  ? row[x0 - 1] : 0.f;
            float d1 = row[x0];
            float d2 = row[x0 + 1];
            float d3 = (t < 63) ? row[x0 + 2] : 0.f;
            comp_v[0][q] = d0 - d2;
            comp_v[1][q] = d1 + d2;
            comp_v[2][q] = d2 - d1;
            comp_v[3][q] = d1 - d3;
        }
        const int pg = y * 8 + pg_rel;
#pragma unroll
        for (int comp = 0; comp < 4; comp++) {
            float h[4], lo[4];
#pragma unroll
            for (int q = 0; q < 4; q++) {
                h[q]  = __half2float(__float2half_rn(comp_v[comp][q]));
                lo[q] = comp_v[comp][q] - h[q];
            }
            uint2 hi2, lo2;
            hi2.x = pack_h2(h[0], h[1]);  lo2.x = pack_h2(lo[0], lo[1]);
            hi2.y = pack_h2(h[2], h[3]);  lo2.y = pack_h2(lo[2], lo[3]);
            const size_t off = (((size_t)(comp * BATCH + n) * 1024 + pg) * 16 + kk) * 32 + l;
            g_bh[off] = hi2;
            g_bl[off] = lo2;
        }
    }
}

// ============================================================
// Kernel 1: conv3x3 via 1D-Winograd F(2,3) + 3-term fp16-split
// m16n8k16 GEMMs. CTA = 128co x 64 pairs (one y-row), 8 warps
// (2m x 4n) of 64co x 16 pairs. 24 stages of K=128
// (comp(4) x r(3) x kk-half(2)), 2-stage cp.async, 96KB/stage
// (192KB total -> 1 CTA/SM, the proven high-efficiency regime).
// grid = dim3(4, 1024).
// ============================================================
#define STAGE_BYTES 98304   // Ah 32K | Al 32K | Bh 16K | Bl 16K
#define A_LO_OFF 32768
#define B_HI_OFF 65536
#define B_LO_OFF 81920

__device__ __forceinline__ void stage_load(
    char* sp, int cn, int t6, int head, int cotile, int n, int pg0, int tid)
{
    const int r   = t6 >> 1;
    const int kk0 = (t6 & 1) * 8;

    // A: 4096 uint4 (hi 2048 + lo 2048), 16 per thread
    const size_t abase = ((size_t)((head * 4 + cn) * 3 + r) * 16 + cotile * 8) * 512;
#pragma unroll
    for (int it = 0; it < 16; it++) {
        const int cid = tid + it * 256;
        const int prec = cid >> 11, cc = cid & 2047;
        const int mgl = cc >> 8, kkl = (cc >> 5) & 7, ll = cc & 31;
        const uint4* src = (prec ? g_wal : g_wah) + abase + mgl * 512 + (kk0 + kkl) * 32 + ll;
        uint32_t dst = (uint32_t)__cvta_generic_to_shared(
            sp + prec * A_LO_OFF + ((mgl * 8 + kkl) * 32 + ll) * 16);
        CP_ASYNC16(dst, src);
    }
    // B: 2048 x 16B chunks (lane-paired uint2s, hi+lo), 8 per thread
    const size_t bbase = (size_t)(cn * BATCH + n) * 1024;
    const int pgsh = pg0 + (r - 1) * 8;
#pragma unroll
    for (int it = 0; it < 8; it++) {
        const int cid = tid + it * 256;
        const int prec = cid >> 10, cc = cid & 1023;
        const int kkl = cc >> 7, pgl = (cc >> 4) & 7, ll2 = cc & 15;
        const int pgsrc = pgsh + pgl;
        const unsigned ok = ((unsigned)pgsrc < 1024u);
        const int pgc = ok ? pgsrc : 0;
        const uint2* src = (prec ? g_bl : g_bh)
            + ((bbase + pgc) * 16 + kk0 + kkl) * 32 + ll2 * 2;
        uint32_t dst = (uint32_t)__cvta_generic_to_shared(
            sp + B_HI_OFF + prec * 16384 + ((kkl * 8 + pgl) * 32 + ll2 * 2) * 8);
        CP_ASYNC16P(dst, src, ok ? 16u : 0u);
    }
}

__global__ __launch_bounds__(256, 1) void conv_wino_kernel()
{
    extern __shared__ char smem[];
    const int tid = threadIdx.x;
    const int lane = tid & 31;
    const int wid = tid >> 5;
    const int warp_m = wid >> 2;       // 0..1 -> 64 co
    const int warp_n = wid & 3;        // 0..3 -> 16 pairs
    const int g = lane >> 2, tig = lane & 3;

    const int head   = blockIdx.x >> 1;
    const int cotile = blockIdx.x & 1;
    const int ptile  = blockIdx.y;     // 0..1023
    const int n      = ptile >> 7;     // image
    const int row    = ptile & 127;    // y
    const int pg0    = row * 8;        // pair-group base (8 pg per row)

    float acc[4][4][2][4];             // [comp][m][np][q]
#pragma unroll
    for (int c4 = 0; c4 < 4; c4++)
#pragma unroll
        for (int m = 0; m < 4; m++)
#pragma unroll
            for (int np = 0; np < 2; np++)
#pragma unroll
                for (int q = 0; q < 4; q++) acc[c4][m][np][q] = 0.f;

    char* buf0 = smem;
    char* buf1 = smem + STAGE_BYTES;

    stage_load(buf0, 0, 0, head, cotile, n, pg0, tid); CP_COMMIT();
    stage_load(buf1, 0, 1, head, cotile, n, pg0, tid); CP_COMMIT();

#pragma unroll
    for (int comp = 0; comp < 4; comp++) {
        for (int t = 0; t < 6; t++) {
            const int sidx = comp * 6 + t;
            CP_WAIT1();
            __syncthreads();
            char* sp = (sidx & 1) ? buf1 : buf0;

#pragma unroll
            for (int kkl = 0; kkl < 8; kkl++) {
                uint4 Ah[4], Al[4];
#pragma unroll
                for (int m = 0; m < 4; m++) {
                    const int mgl = warp_m * 4 + m;
                    Ah[m] = *(const uint4*)(sp + ((mgl * 8 + kkl) * 32 + lane) * 16);
                    Al[m] = *(const uint4*)(sp + A_LO_OFF + ((mgl * 8 + kkl) * 32 + lane) * 16);
                }
#pragma unroll
                for (int np = 0; np < 2; np++) {
                    const int pgl = warp_n * 2 + np;
                    uint2 bh = *(const uint2*)(sp + B_HI_OFF + ((kkl * 8 + pgl) * 32 + lane) * 8);
                    uint2 bl = *(const uint2*)(sp + B_LO_OFF + ((kkl * 8 + pgl) * 32 + lane) * 8);
#pragma unroll
                    for (int m = 0; m < 4; m++) {
                        MMA_FP16(acc[comp][m][np], Ah[m], bh.x, bh.y);
                        MMA_FP16(acc[comp][m][np], Al[m], bh.x, bh.y);
                        MMA_FP16(acc[comp][m][np], Ah[m], bl.x, bl.y);
                    }
                }
            }
            __syncthreads();
            if (sidx + 2 < 24) {
                int tn = t + 2, cn = comp;
                if (tn >= 6) { tn -= 6; cn += 1; }
                stage_load((sidx & 1) ? buf1 : buf0, cn, tn, head, cotile, n, pg0, tid);
            }
            CP_COMMIT();
        }
    }

    // Winograd recombine + store: y0 = A0+A1+A2, y1 = A1-A2-A3.
    // frag q: q0=(row g, pair 2tig), q1=(g, 2tig+1), q2=(g+8, 2tig), q3=(g+8, 2tig+1)
    float* outb = head ? g_hs : g_hd;
#pragma unroll
    for (int m = 0; m < 4; m++) {
#pragma unroll
        for (int np = 0; np < 2; np++) {
            const int pxb = warp_n * 32 + np * 16 + tig * 4;
#pragma unroll
            for (int half = 0; half < 2; half++) {   // rows g, g+8
                const int co = cotile * 128 + (warp_m * 4 + m) * 16 + g + half * 8;
                const int q0 = half * 2, q1 = half * 2 + 1;
                float y00 = acc[0][m][np][q0] + acc[1][m][np][q0] + acc[2][m][np][q0];
                float y10 = acc[1][m][np][q0] - acc[2][m][np][q0] - acc[3][m][np][q0];
                float y01 = acc[0][m][np][q1] + acc[1][m][np][q1] + acc[2][m][np][q1];
                float y11 = acc[1][m][np][q1] - acc[2][m][np][q1] - acc[3][m][np][q1];
                float* dst = outb + ((size_t)(n * CH + co)) * HW + row * WW + pxb;
                *(float4*)dst = make_float4(y00, y10, y01, y11);
            }
        }
    }
}

// ============================================================
// Kernel 2a/2b: GroupNorm stats, two-phase.
// ============================================================
__global__ __launch_bounds__(256) void gn_partA_kernel()
{
    const int id = blockIdx.x;               // ((head*8+b)*8+g)*16+slice
    const int head = id >> 10;
    const int b = (id >> 7) & 7;
    const int g = (id >> 4) & 7;
    const int sl = id & 15;
    const float4* p4 = (const float4*)((head ? g_hs : g_hd)
                     + ((size_t)(b * CH + g * CPG)) * HW + sl * 32768);
    const int tid = threadIdx.x;
    float s = 0.f, s2 = 0.f;
    for (int i = tid; i < 8192; i += 256) {
        float4 v = p4[i];
        s += (v.x + v.y) + (v.z + v.w);
        s2 = fmaf(v.x, v.x, fmaf(v.y, v.y, fmaf(v.z, v.z, fmaf(v.w, v.w, s2))));
    }
    __shared__ float sh[256], sh2[256];
    sh[tid] = s; sh2[tid] = s2;
    __syncthreads();
    for (int off = 128; off > 0; off >>= 1) {
        if (tid < off) { sh[tid] += sh[tid + off]; sh2[tid] += sh2[tid + off]; }
        __syncthreads();
    }
    if (tid == 0) { g_part[id * 2] = sh[0]; g_part[id * 2 + 1] = sh2[0]; }
}

__global__ void gn_partB_kernel()
{
    const int t = threadIdx.x;
    if (t >= 128) return;
    float s = 0.f, s2 = 0.f;
    for (int i = 0; i < 16; i++) {
        s  += g_part[(t * 16 + i) * 2];
        s2 += g_part[(t * 16 + i) * 2 + 1];
    }
    const float mu = s / 524288.f;
    const float var = s2 / 524288.f - mu * mu;
    g_stats[t * 2] = mu;
    g_stats[t * 2 + 1] = rsqrtf(var + 1e-5f);
}

// ============================================================
// Kernel 3: per-pixel epilogue. GN affine + exact GELU + 1x1 convs
// + sigmoid/CORN decode/normalize/labels.
// ============================================================
__global__ __launch_bounds__(256) void epilogue_kernel(
    const float* __restrict__ dgs, const float* __restrict__ dgb,
    const float* __restrict__ dw2, const float* __restrict__ db2,
    const float* __restrict__ sgs, const float* __restrict__ sgb,
    const float* __restrict__ sw2, const float* __restrict__ sb2,
    float* __restrict__ out)
{
    __shared__ float s_dgs[CH], s_dgb[CH], s_dw2[CH];
    __shared__ float s_sgs[CH], s_sgb[CH], s_sw0[CH], s_sw1[CH];
    __shared__ float s_mu[2][NGRP], s_rs[2][NGRP];

    const int tid = threadIdx.x;
    const int p   = blockIdx.x * 256 + tid;
    const int n   = p >> 14;
    const int pix = p & 16383;

    for (int c = tid; c < CH; c += 256) {
        s_dgs[c] = dgs[c]; s_dgb[c] = dgb[c]; s_dw2[c] = dw2[c];
        s_sgs[c] = sgs[c]; s_sgb[c] = sgb[c];
        s_sw0[c] = sw2[c]; s_sw1[c] = sw2[CH + c];
    }
    if (tid < 16) {
        int h = tid >> 3, g = tid & 7;
        int idx = ((h * BATCH + n) * NGRP + g) * 2;
        s_mu[h][g] = g_stats[idx];
        s_rs[h][g] = g_stats[idx + 1];
    }
    __syncthreads();

    const float* hd = g_hd + (size_t)n * CH * HW + pix;
    const float* hs = g_hs + (size_t)n * CH * HW + pix;

    float dl = 0.f, sl0 = 0.f, sl1 = 0.f;
#pragma unroll 4
    for (int c = 0; c < CH; c++) {
        const int g = c >> 5;
        float v  = hd[(size_t)c * HW];
        float xn = fmaf((v - s_mu[0][g]) * s_rs[0][g], s_dgs[c], s_dgb[c]);
        float ge = xn * normcdff(xn);
        dl = fmaf(ge, s_dw2[c], dl);

        v  = hs[(size_t)c * HW];
        xn = fmaf((v - s_mu[1][g]) * s_rs[1][g], s_sgs[c], s_sgb[c]);
        ge = xn * normcdff(xn);
        sl0 = fmaf(ge, s_sw0[c], sl0);
        sl1 = fmaf(ge, s_sw1[c], sl1);
    }
    dl  += db2[0];
    sl0 += sb2[0];
    sl1 += sb2[1];

    const float pd = 1.f / (1.f + expf(-dl));
    const float t0 = 1.f / (1.f + expf(-sl0));
    const float t1 = t0 * (1.f / (1.f + expf(-sl1)));
    float sev0 = fmaxf(1.f - t0, 1e-8f);
    float sev1 = fmaxf(t0 - t1, 1e-8f);
    float sev2 = fmaxf(t1,       1e-8f);
    const float ssum = fmaxf(sev0 + sev1 + sev2, 1e-8f);
    sev0 /= ssum; sev1 /= ssum; sev2 /= ssum;

    float px0 = fmaxf(1.f - pd,   1e-8f);
    float px1 = fmaxf(pd * sev0,  1e-8f);
    float px2 = fmaxf(pd * sev1,  1e-8f);
    float px3 = fmaxf(pd * sev2,  1e-8f);
    const float psum = fmaxf(px0 + px1 + px2 + px3, 1e-8f);
    px0 /= psum; px1 /= psum; px2 /= psum; px3 /= psum;

    int sp = 0; float bm = sev0;
    if (sev1 > bm) { bm = sev1; sp = 1; }
    if (sev2 > bm) { bm = sev2; sp = 2; }
    const int lbl = (pd >= 0.5f) ? (sp + 1) : 0;

    out[O_DMG  + n * HW + pix]            = dl;
    out[O_CORN + (n * 2 + 0) * HW + pix]  = sl0;
    out[O_CORN + (n * 2 + 1) * HW + pix]  = sl1;
    out[O_PIX  + (n * 4 + 0) * HW + pix]  = px0;
    out[O_PIX  + (n * 4 + 1) * HW + pix]  = px1;
    out[O_PIX  + (n * 4 + 2) * HW + pix]  = px2;
    out[O_PIX  + (n * 4 + 3) * HW + pix]  = px3;
    out[O_PRED + n * HW + pix]            = (float)lbl;
}

// ============================================================
// Kernel 4: masked mean + exact top-k sum per (b,c). 32 blocks.
// ============================================================
__global__ __launch_bounds__(256) void reduce_topk_kernel(
    const float* __restrict__ mask, const float* __restrict__ pix)
{
    extern __shared__ unsigned skey[];
    __shared__ int   ibuf[256];
    __shared__ float fbuf[256];

    const int tid = threadIdx.x;
    const int b = blockIdx.x >> 2;
    const int c = blockIdx.x & 3;
    const float* pv = pix  + ((size_t)b * 4 + c) * HW;
    const float* mk = mask + (size_t)b * HW;

    for (int i = tid; i < HW; i += 256)
        skey[i] = (mk[i] > 0.5f) ? __float_as_uint(pv[i]) : 0u;
    __syncthreads();

    int   mc = 0;
    float ms = 0.f;
    for (int i = tid; i < HW; i += 256) {
        unsigned kk = skey[i];
        if (kk) { mc++; ms += __uint_as_float(kk); }
    }
    ibuf[tid] = mc; fbuf[tid] = ms;
    __syncthreads();
    for (int off = 128; off > 0; off >>= 1) {
        if (tid < off) { ibuf[tid] += ibuf[tid + off]; fbuf[tid] += fbuf[tid + off]; }
        __syncthreads();
    }
    const int   cnt    = ibuf[0];
    const float sumall = fbuf[0];
    __syncthreads();

    int k = (int)rintf((float)cnt * 0.2f);
    if (k < 1) k = 1;
    const int cmax = (cnt > 1) ? cnt : 1;
    if (k > cmax) k = cmax;

    unsigned prefix = 0u;
    for (int bit = 30; bit >= 0; bit--) {
        const unsigned cand = prefix | (1u << bit);
        int cl = 0;
        for (int i = tid; i < HW; i += 256)
            if (skey[i] >= cand) cl++;
        ibuf[tid] = cl;
        __syncthreads();
        for (int off = 128; off > 0; off >>= 1) {
            if (tid < off) ibuf[tid] += ibuf[tid + off];
            __syncthreads();
        }
        if (ibuf[0] >= k) prefix = cand;
        __syncthreads();
    }

    int   cg = 0;
    float sg = 0.f;
    for (int i = tid; i < HW; i += 256) {
        unsigned kk = skey[i];
        if (kk > prefix) { cg++; sg += __uint_as_float(kk); }
    }
    ibuf[tid] = cg; fbuf[tid] = sg;
    __syncthreads();
    for (int off = 128; off > 0; off >>= 1) {
        if (tid < off) { ibuf[tid] += ibuf[tid + off]; fbuf[tid] += fbuf[tid + off]; }
        __syncthreads();
    }
    if (tid == 0) {
        const float T = __uint_as_float(prefix);
        const float topsum = fbuf[0] + (float)(k - ibuf[0]) * T;
        g_mean_raw[b * 4 + c] = sumall / (float)((cnt > 1) ? cnt : 1);
        g_topk_raw[b * 4 + c] = topsum / (float)k;
        g_cnt[b] = cnt;
    }
}

// ============================================================
// Kernel 5: finalize
// ============================================================
__global__ void finalize_kernel(float* __restrict__ out)
{
    const int b = threadIdx.x;
    if (b >= BATCH) return;
    const int cnt = g_cnt[b];

    float m[4], t[4], a[4];
    float sm = 0.f, st = 0.f;
    for (int c = 0; c < 4; c++) {
        m[c] = (cnt == 0) ? 0.25f : fmaxf(g_mean_raw[b * 4 + c], 1e-8f);
        t[c] = (cnt == 0) ? 0.25f : fmaxf(g_topk_raw[b * 4 + c], 1e-8f);
        sm += m[c]; st += t[c];
    }
    sm = fmaxf(sm, 1e-8f); st = fmaxf(st, 1e-8f);
    float sa = 0.f;
    for (int c = 0; c < 4; c++) {
        m[c] /= sm; t[c] /= st;
        a[c] = fmaxf(0.7f * m[c] + 0.3f * t[c], 1e-8f);
        sa += a[c];
    }
    sa = fmaxf(sa, 1e-8f);
    int best = 0; float bv = -1.f;
    for (int c = 0; c < 4; c++) {
        a[c] /= sa;
        if (a[c] > bv) { bv = a[c]; best = c; }
        out[O_MEAN + b * 4 + c] = m[c];
        out[O_TOPK + b * 4 + c] = t[c];
        out[O_AGG  + b * 4 + c] = a[c];
    }
    out[O_AGGL + b] = (float)best;
}

// ============================================================
extern "C" void kernel_launch(void* const* d_in, const int* in_sizes, int n_in,
                              void* d_out, int out_size)
{
    const float* fm   = (const float*)d_in[0];
    const float* mask = (const float*)d_in[1];
    const float* dw1  = (const float*)d_in[2];
    const float* dgs  = (const float*)d_in[3];
    const float* dgb  = (const float*)d_in[4];
    const float* dw2  = (const float*)d_in[5];
    const float* db2  = (const float*)d_in[6];
    const float* sw1  = (const float*)d_in[7];
    const float* sgs  = (const float*)d_in[8];
    const float* sgb  = (const float*)d_in[9];
    const float* sw2  = (const float*)d_in[10];
    const float* sb2  = (const float*)d_in[11];
    float* out = (float*)d_out;

    cudaFuncSetAttribute(conv_wino_kernel,
                         cudaFuncAttributeMaxDynamicSharedMemorySize, 2 * STAGE_BYTES);
    cudaFuncSetAttribute(convert_in_kernel,
                         cudaFuncAttributeMaxDynamicSharedMemorySize, 128 * TP * 4);
    cudaFuncSetAttribute(reduce_topk_kernel,
                         cudaFuncAttributeMaxDynamicSharedMemorySize, HW * 4);

    convert_w_kernel<<<dim3(32, 12, 2), 256>>>(dw1, sw1);
    convert_in_kernel<<<dim3(2, 128, 8), 256, 128 * TP * 4>>>(fm);
    conv_wino_kernel<<<dim3(4, 1024), 256, 2 * STAGE_BYTES>>>();
    gn_partA_kernel<<<2048, 256>>>();
    gn_partB_kernel<<<1, 128>>>();
    epilogue_kernel<<<NPIX / 256, 256>>>(dgs, dgb, dw2, db2, sgs, sgb, sw2, sb2, out);
    reduce_topk_kernel<<<BATCH * 4, 256, HW * 4>>>(mask, out + O_PIX);
    finalize_kernel<<<1, 32>>>(out);
}

// round 17
// speedup vs baseline: 2.2866x; 1.1767x over previous
#include <cuda_runtime.h>
#include <cuda_fp16.h>
#include <math.h>
#include <stdint.h>

#define BATCH 8
#define CIN   256
#define CH    256
#define HH    128
#define WW    128
#define HW    (HH*WW)
#define NPIX  (BATCH*HW)
#define NGRP  8
#define CPG   32

#define O_DMG   0
#define O_CORN  131072
#define O_PIX   393216
#define O_PRED  917504
#define O_MEAN  1048576
#define O_TOPK  1048608
#define O_AGG   1048640
#define O_AGGL  1048672

__device__ float g_hd[(size_t)BATCH*CH*HW];
__device__ float g_hs[(size_t)BATCH*CH*HW];
// F(4,3) weights: plane=((head*6+comp)*3+r); [plane][mg16][kk16][lane32] uint4
__device__ uint4 g_wah[2*6*3*16*16*32];
__device__ uint4 g_wal[2*6*3*16*16*32];
// F(4,3) inputs: [(comp*8+n)][qg512][kk16][lane32] uint2
__device__ __align__(16) uint2 g_bh[(size_t)6*8*512*16*32];
__device__ __align__(16) uint2 g_bl[(size_t)6*8*512*16*32];
__device__ float g_part[2048*2];
__device__ float g_stats[2*BATCH*NGRP*2];
__device__ float g_mean_raw[BATCH*4];
__device__ float g_topk_raw[BATCH*4];
__device__ int   g_cnt[BATCH];

#define MMA_FP16(c, a, b0, b1) \
    asm volatile("mma.sync.aligned.m16n8k16.row.col.f32.f16.f16.f32 " \
        "{%0,%1,%2,%3},{%4,%5,%6,%7},{%8,%9},{%0,%1,%2,%3};" \
        : "+f"((c)[0]), "+f"((c)[1]), "+f"((c)[2]), "+f"((c)[3]) \
        : "r"((a).x), "r"((a).y), "r"((a).z), "r"((a).w), "r"(b0), "r"(b1))
#define CP_ASYNC16(dst, src) \
    asm volatile("cp.async.cg.shared.global [%0], [%1], 16;" :: "r"(dst), "l"(src) : "memory")
#define CP_ASYNC16P(dst, src, sz) \
    asm volatile("cp.async.cg.shared.global [%0], [%1], 16, %2;" :: "r"(dst), "l"(src), "r"(sz) : "memory")
#define CP_COMMIT()  asm volatile("cp.async.commit_group;" ::: "memory")
#define CP_WAIT1()   asm volatile("cp.async.wait_group 1;" ::: "memory")

__device__ __forceinline__ uint32_t pack_h2(float a, float b) {
    __half2 h = __halves2half2(__float2half_rn(a), __float2half_rn(b));
    return *reinterpret_cast<uint32_t*>(&h);
}

// Kernel 0a: F(4,3) weight transform + fp16 split. grid (32, 18, 2).
__global__ __launch_bounds__(256) void convert_w_kernel(
    const float* __restrict__ dw1, const float* __restrict__ sw1)
{
    const int i = blockIdx.x * 256 + threadIdx.x;
    const int mg = i >> 9, kk = (i >> 5) & 15, l = i & 31;
    const int g = l >> 2, tig = l & 3;
    const int head = blockIdx.z;
    const int comp = blockIdx.y / 3, r = blockIdx.y - comp * 3;
    const float* w = head ? sw1 : dw1;

    float a0, a1, a2;
    if      (comp == 0) { a0 = 0.25f;    a1 = 0.f;       a2 = 0.f;      }
    else if (comp == 1) { a0 = -1.f/6.f; a1 = -1.f/6.f;  a2 = -1.f/6.f; }
    else if (comp == 2) { a0 = -1.f/6.f; a1 = 1.f/6.f;   a2 = -1.f/6.f; }
    else if (comp == 3) { a0 = 1.f/24.f; a1 = 1.f/12.f;  a2 = 1.f/6.f;  }
    else if (comp == 4) { a0 = 1.f/24.f; a1 = -1.f/12.f; a2 = 1.f/6.f;  }
    else                { a0 = 0.f;      a1 = 0.f;       a2 = 1.f;      }

    const int co0 = mg * 16 + g;
    const int ciA = kk * 16 + 2 * tig, ciB = ciA + 8;
    const int cos[8] = {co0, co0, co0 + 8, co0 + 8, co0, co0, co0 + 8, co0 + 8};
    const int cis[8] = {ciA, ciA + 1, ciA, ciA + 1, ciB, ciB + 1, ciB, ciB + 1};

    float v[8], h[8], lo[8];
#pragma unroll
    for (int q = 0; q < 8; q++) {
        const float* wp = w + ((size_t)(cos[q] * CIN + cis[q]) * 3 + r) * 3;
        v[q] = a0 * wp[0] + a1 * wp[1] + a2 * wp[2];
        h[q]  = __half2float(__float2half_rn(v[q]));
        lo[q] = v[q] - h[q];
    }
    uint4 hi4, lo4;
    hi4.x = pack_h2(h[0], h[1]);  lo4.x = pack_h2(lo[0], lo[1]);
    hi4.y = pack_h2(h[2], h[3]);  lo4.y = pack_h2(lo[2], lo[3]);
    hi4.z = pack_h2(h[4], h[5]);  lo4.z = pack_h2(lo[4], lo[5]);
    hi4.w = pack_h2(h[6], h[7]);  lo4.w = pack_h2(lo[6], lo[7]);
    const size_t off = (size_t)(((head * 6 + comp) * 3 + r) * 16 + mg) * 512 + kk * 32 + l;
    g_wah[off] = hi4;
    g_wal[off] = lo4;
}

// Kernel 0b: input -> F(4,3) components c0..c5, fp16 split, frag-permuted.
// grid (4 ci-quads, 128 y, 8 n), 256 thr. d_k = in[x=4t-1+k], k=0..5.
__global__ __launch_bounds__(256) void convert_in_kernel(const float* __restrict__ in)
{
    __shared__ float tile[64 * 132];
    const int ciq = blockIdx.x, y = blockIdx.y, n = blockIdx.z;
    const int ci0 = ciq * 64;
    const int tid = threadIdx.x;
    {
        const int c = tid >> 2, xs = (tid & 3) * 32;
        const float* src = in + ((size_t)(n * CIN + ci0 + c)) * HW + y * WW + xs;
        float* drow = tile + c * 132 + xs;
        const float4* s4 = (const float4*)src;
#pragma unroll
        for (int j = 0; j < 8; j++)
            *(float4*)(drow + j * 4) = s4[j];
    }
    __syncthreads();

    const int l = tid & 31;
    const int g = l >> 2, tig = l & 3;
    const int kkr  = (tid >> 5) & 3;
    const int half = tid >> 7;
    const int cb = kkr * 16 + 2 * tig;
    const int cs[4] = {cb, cb + 1, cb + 8, cb + 9};

#pragma unroll
    for (int ho = 0; ho < 2; ho++) {
        const int oct = half * 2 + ho;
        const int t4  = oct * 8 + g;
        const int x0  = 4 * t4 - 1;
        float cvv[6][4];
#pragma unroll
        for (int q = 0; q < 4; q++) {
            const float* row = tile + cs[q] * 132;
            float d[6];
#pragma unroll
            for (int k = 0; k < 6; k++) {
                const int x = x0 + k;
                d[k] = ((unsigned)x < 128u) ? row[x] : 0.f;
            }
            cvv[0][q] = fmaf(4.f, d[0], fmaf(-5.f, d[2], d[4]));
            cvv[1][q] = (d[3] + d[4]) - 4.f * (d[1] + d[2]);
            cvv[2][q] = fmaf(4.f, d[1] - d[2], d[4] - d[3]);
            cvv[3][q] = fmaf(2.f, d[3] - d[1], d[4] - d[2]);
            cvv[4][q] = fmaf(2.f, d[1] - d[3], d[4] - d[2]);
            cvv[5][q] = fmaf(4.f, d[1], fmaf(-5.f, d[3], d[5]));
        }
        const int qg = y * 4 + oct;
#pragma unroll
        for (int comp = 0; comp < 6; comp++) {
            float h[4], lo[4];
#pragma unroll
            for (int q = 0; q < 4; q++) {
                h[q]  = __half2float(__float2half_rn(cvv[comp][q]));
                lo[q] = cvv[comp][q] - h[q];
            }
            uint2 hi2, lo2;
            hi2.x = pack_h2(h[0], h[1]);  lo2.x = pack_h2(lo[0], lo[1]);
            hi2.y = pack_h2(h[2], h[3]);  lo2.y = pack_h2(lo[2], lo[3]);
            const size_t off = ((size_t)((comp * 8 + n) * 512 + qg)) * 512
                             + (ciq * 4 + kkr) * 32 + l;
            g_bh[off] = hi2;
            g_bl[off] = lo2;
        }
    }
}

// Kernel 1: conv3x3 via F(4,3) Winograd, 3-term fp16-split m16n8k16.
// CTA = 128co x 64 quad4s (2 y-rows), 8 warps (2m x 4n). 36 stages
// (6 comp x 3 r x 2 K-half), K=128/stage, 96KB/stage, 192KB, 1 CTA/SM.
// grid = dim3(4, 512).
#define STAGE_BYTES 98304
#define A_LO_OFF 32768
#define B_HI_OFF 65536
#define B_LO_OFF 81920

__device__ __forceinline__ void stage_load(
    char* sp, int comp, int rkk, int head, int cotile, int n, int qg0, int tid)
{
    const int r   = rkk >> 1;
    const int kk0 = (rkk & 1) * 8;
    const size_t abase = (size_t)(((head * 6 + comp) * 3 + r) * 16 + cotile * 8) * 512;
#pragma unroll
    for (int it = 0; it < 16; it++) {
        const int cid = tid + it * 256;
        const int prec = cid >> 11, cc = cid & 2047;
        const int mgl = cc >> 8, kkl = (cc >> 5) & 7, ll = cc & 31;
        const uint4* src = (prec ? g_wal : g_wah) + abase + mgl * 512 + (kk0 + kkl) * 32 + ll;
        uint32_t dst = (uint32_t)__cvta_generic_to_shared(
            sp + prec * A_LO_OFF + ((mgl * 8 + kkl) * 32 + ll) * 16);
        CP_ASYNC16(dst, src);
    }
    const size_t bbase = (size_t)((comp * 8 + n) * 512);
    const int qsh = qg0 + (r - 1) * 4;
#pragma unroll
    for (int it = 0; it < 8; it++) {
        const int cid = tid + it * 256;
        const int prec = cid >> 10, cc = cid & 1023;
        const int qgl = cc >> 7, kkl = (cc >> 4) & 7, lp = cc & 15;
        const int qs = qsh + qgl;
        const unsigned ok = ((unsigned)qs < 512u);
        const int qc = ok ? qs : 0;
        const uint2* src = (prec ? g_bl : g_bh)
            + (bbase + qc) * 512 + (kk0 + kkl) * 32 + lp * 2;
        uint32_t dst = (uint32_t)__cvta_generic_to_shared(
            sp + B_HI_OFF + prec * 16384 + ((qgl * 8 + kkl) * 32 + lp * 2) * 8);
        CP_ASYNC16P(dst, src, ok ? 16u : 0u);
    }
}

__global__ __launch_bounds__(256, 1) void conv_wino_kernel()
{
    extern __shared__ char smem[];
    const int tid = threadIdx.x;
    const int lane = tid & 31;
    const int wid = tid >> 5;
    const int warp_m = wid >> 2;
    const int warp_n = wid & 3;
    const int g = lane >> 2, tig = lane & 3;

    const int head   = blockIdx.x >> 1;
    const int cotile = blockIdx.x & 1;
    const int by     = blockIdx.y;
    const int n      = by >> 6;
    const int qt     = by & 63;
    const int qg0    = qt * 8;

    float yk[4][4][2][4];
    float mc[4][2][4];
#pragma unroll
    for (int k = 0; k < 4; k++)
#pragma unroll
        for (int mm = 0; mm < 4; mm++)
#pragma unroll
            for (int np = 0; np < 2; np++)
#pragma unroll
                for (int q = 0; q < 4; q++) yk[k][mm][np][q] = 0.f;
#pragma unroll
    for (int mm = 0; mm < 4; mm++)
#pragma unroll
        for (int np = 0; np < 2; np++)
#pragma unroll
            for (int q = 0; q < 4; q++) mc[mm][np][q] = 0.f;

    char* buf0 = smem;
    char* buf1 = smem + STAGE_BYTES;

    stage_load(buf0, 0, 0, head, cotile, n, qg0, tid); CP_COMMIT();
    stage_load(buf1, 0, 1, head, cotile, n, qg0, tid); CP_COMMIT();

#pragma unroll
    for (int comp = 0; comp < 6; comp++) {
        for (int rkk = 0; rkk < 6; rkk++) {
            const int sidx = comp * 6 + rkk;
            CP_WAIT1();
            __syncthreads();
            char* sp = (sidx & 1) ? buf1 : buf0;
#pragma unroll
            for (int kk = 0; kk < 8; kk++) {
                uint4 Ah[4], Al[4];
#pragma unroll
                for (int mm = 0; mm < 4; mm++) {
                    const int mgl = warp_m * 4 + mm;
                    Ah[mm] = *(const uint4*)(sp + ((mgl * 8 + kk) * 32 + lane) * 16);
                    Al[mm] = *(const uint4*)(sp + A_LO_OFF + ((mgl * 8 + kk) * 32 + lane) * 16);
                }
#pragma unroll
                for (int np = 0; np < 2; np++) {
                    const int qgl = warp_n * 2 + np;
                    uint2 bh = *(const uint2*)(sp + B_HI_OFF + ((qgl * 8 + kk) * 32 + lane) * 8);
                    uint2 bl = *(const uint2*)(sp + B_LO_OFF + ((qgl * 8 + kk) * 32 + lane) * 8);
#pragma unroll
                    for (int mm = 0; mm < 4; mm++) {
                        MMA_FP16(mc[mm][np], Ah[mm], bh.x, bh.y);
                        MMA_FP16(mc[mm][np], Al[mm], bh.x, bh.y);
                        MMA_FP16(mc[mm][np], Ah[mm], bl.x, bl.y);
                    }
                }
            }
            __syncthreads();
            if (sidx + 2 < 36) {
                int rn = rkk + 2, cn = comp;
                if (rn >= 6) { rn -= 6; cn += 1; }
                stage_load((sidx & 1) ? buf1 : buf0, cn, rn, head, cotile, n, qg0, tid);
            }
            CP_COMMIT();
        }
        // fold component into outputs: A^T rows (1,1,1,1,1,0 / 0,1,-1,2,-2,0 /
        // 0,1,1,4,4,0 / 0,1,-1,8,-8,1)
#pragma unroll
        for (int mm = 0; mm < 4; mm++)
#pragma unroll
            for (int np = 0; np < 2; np++)
#pragma unroll
                for (int q = 0; q < 4; q++) {
                    const float v = mc[mm][np][q];
                    if (comp == 0) {
                        yk[0][mm][np][q] += v;
                    } else if (comp == 1) {
                        yk[0][mm][np][q] += v; yk[1][mm][np][q] += v;
                        yk[2][mm][np][q] += v; yk[3][mm][np][q] += v;
                    } else if (comp == 2) {
                        yk[0][mm][np][q] += v; yk[1][mm][np][q] -= v;
                        yk[2][mm][np][q] += v; yk[3][mm][np][q] -= v;
                    } else if (comp == 3) {
                        yk[0][mm][np][q] += v;
                        yk[1][mm][np][q] = fmaf(2.f, v, yk[1][mm][np][q]);
                        yk[2][mm][np][q] = fmaf(4.f, v, yk[2][mm][np][q]);
                        yk[3][mm][np][q] = fmaf(8.f, v, yk[3][mm][np][q]);
                    } else if (comp == 4) {
                        yk[0][mm][np][q] += v;
                        yk[1][mm][np][q] = fmaf(-2.f, v, yk[1][mm][np][q]);
                        yk[2][mm][np][q] = fmaf(4.f, v, yk[2][mm][np][q]);
                        yk[3][mm][np][q] = fmaf(-8.f, v, yk[3][mm][np][q]);
                    } else {
                        yk[3][mm][np][q] += v;
                    }
                    mc[mm][np][q] = 0.f;
                }
    }

    // Store: frag col c (=2tig, 2tig+1) -> quad4 oct*8+c -> x = oct*32+4c.
    float* outb = head ? g_hs : g_hd;
#pragma unroll
    for (int mm = 0; mm < 4; mm++) {
#pragma unroll
        for (int np = 0; np < 2; np++) {
            const int qg = qg0 + warp_n * 2 + np;
            const int yrow = qg >> 2, oct = qg & 3;
            const int xA = oct * 32 + 8 * tig;
#pragma unroll
            for (int half = 0; half < 2; half++) {
                const int co = cotile * 128 + (warp_m * 4 + mm) * 16 + g + half * 8;
                const int qA = half * 2, qB = half * 2 + 1;
                float* dst = outb + ((size_t)(n * CH + co)) * HW + yrow * WW + xA;
                *(float4*)dst = make_float4(yk[0][mm][np][qA], yk[1][mm][np][qA],
                                            yk[2][mm][np][qA], yk[3][mm][np][qA]);
                *(float4*)(dst + 4) = make_float4(yk[0][mm][np][qB], yk[1][mm][np][qB],
                                                  yk[2][mm][np][qB], yk[3][mm][np][qB]);
            }
        }
    }
}

// Kernel 2a/2b: GroupNorm stats, two-phase.
__global__ __launch_bounds__(256) void gn_partA_kernel()
{
    const int id = blockIdx.x;
    const int head = id >> 10;
    const int b = (id >> 7) & 7;
    const int g = (id >> 4) & 7;
    const int sl = id & 15;
    const float4* p4 = (const float4*)((head ? g_hs : g_hd)
                     + ((size_t)(b * CH + g * CPG)) * HW + sl * 32768);
    const int tid = threadIdx.x;
    float s = 0.f, s2 = 0.f;
    for (int i = tid; i < 8192; i += 256) {
        float4 v = p4[i];
        s += (v.x + v.y) + (v.z + v.w);
        s2 = fmaf(v.x, v.x, fmaf(v.y, v.y, fmaf(v.z, v.z, fmaf(v.w, v.w, s2))));
    }
    __shared__ float sh[256], sh2[256];
    sh[tid] = s; sh2[tid] = s2;
    __syncthreads();
    for (int off = 128; off > 0; off >>= 1) {
        if (tid < off) { sh[tid] += sh[tid + off]; sh2[tid] += sh2[tid + off]; }
        __syncthreads();
    }
    if (tid == 0) { g_part[id * 2] = sh[0]; g_part[id * 2 + 1] = sh2[0]; }
}

__global__ void gn_partB_kernel()
{
    const int t = threadIdx.x;
    if (t >= 128) return;
    float s = 0.f, s2 = 0.f;
    for (int i = 0; i < 16; i++) {
        s  += g_part[(t * 16 + i) * 2];
        s2 += g_part[(t * 16 + i) * 2 + 1];
    }
    const float mu = s / 524288.f;
    const float var = s2 / 524288.f - mu * mu;
    g_stats[t * 2] = mu;
    g_stats[t * 2 + 1] = rsqrtf(var + 1e-5f);
}

// Kernel 3: per-pixel epilogue.
__global__ __launch_bounds__(256) void epilogue_kernel(
    const float* __restrict__ dgs, const float* __restrict__ dgb,
    const float* __restrict__ dw2, const float* __restrict__ db2,
    const float* __restrict__ sgs, const float* __restrict__ sgb,
    const float* __restrict__ sw2, const float* __restrict__ sb2,
    float* __restrict__ out)
{
    __shared__ float s_dgs[CH], s_dgb[CH], s_dw2[CH];
    __shared__ float s_sgs[CH], s_sgb[CH], s_sw0[CH], s_sw1[CH];
    __shared__ float s_mu[2][NGRP], s_rs[2][NGRP];

    const int tid = threadIdx.x;
    const int p   = blockIdx.x * 256 + tid;
    const int n   = p >> 14;
    const int pix = p & 16383;

    for (int c = tid; c < CH; c += 256) {
        s_dgs[c] = dgs[c]; s_dgb[c] = dgb[c]; s_dw2[c] = dw2[c];
        s_sgs[c] = sgs[c]; s_sgb[c] = sgb[c];
        s_sw0[c] = sw2[c]; s_sw1[c] = sw2[CH + c];
    }
    if (tid < 16) {
        int h = tid >> 3, g = tid & 7;
        int idx = ((h * BATCH + n) * NGRP + g) * 2;
        s_mu[h][g] = g_stats[idx];
        s_rs[h][g] = g_stats[idx + 1];
    }
    __syncthreads();

    const float* hd = g_hd + (size_t)n * CH * HW + pix;
    const float* hs = g_hs + (size_t)n * CH * HW + pix;

    float dl = 0.f, sl0 = 0.f, sl1 = 0.f;
#pragma unroll 4
    for (int c = 0; c < CH; c++) {
        const int g = c >> 5;
        float v  = hd[(size_t)c * HW];
        float xn = fmaf((v - s_mu[0][g]) * s_rs[0][g], s_dgs[c], s_dgb[c]);
        float ge = xn * normcdff(xn);
        dl = fmaf(ge, s_dw2[c], dl);

        v  = hs[(size_t)c * HW];
        xn = fmaf((v - s_mu[1][g]) * s_rs[1][g], s_sgs[c], s_sgb[c]);
        ge = xn * normcdff(xn);
        sl0 = fmaf(ge, s_sw0[c], sl0);
        sl1 = fmaf(ge, s_sw1[c], sl1);
    }
    dl  += db2[0];
    sl0 += sb2[0];
    sl1 += sb2[1];

    const float pd = 1.f / (1.f + expf(-dl));
    const float t0 = 1.f / (1.f + expf(-sl0));
    const float t1 = t0 * (1.f / (1.f + expf(-sl1)));
    float sev0 = fmaxf(1.f - t0, 1e-8f);
    float sev1 = fmaxf(t0 - t1, 1e-8f);
    float sev2 = fmaxf(t1,       1e-8f);
    const float ssum = fmaxf(sev0 + sev1 + sev2, 1e-8f);
    sev0 /= ssum; sev1 /= ssum; sev2 /= ssum;

    float px0 = fmaxf(1.f - pd,   1e-8f);
    float px1 = fmaxf(pd * sev0,  1e-8f);
    float px2 = fmaxf(pd * sev1,  1e-8f);
    float px3 = fmaxf(pd * sev2,  1e-8f);
    const float psum = fmaxf(px0 + px1 + px2 + px3, 1e-8f);
    px0 /= psum; px1 /= psum; px2 /= psum; px3 /= psum;

    int sp = 0; float bm = sev0;
    if (sev1 > bm) { bm = sev1; sp = 1; }
    if (sev2 > bm) { bm = sev2; sp = 2; }
    const int lbl = (pd >= 0.5f) ? (sp + 1) : 0;

    out[O_DMG  + n * HW + pix]            = dl;
    out[O_CORN + (n * 2 + 0) * HW + pix]  = sl0;
    out[O_CORN + (n * 2 + 1) * HW + pix]  = sl1;
    out[O_PIX  + (n * 4 + 0) * HW + pix]  = px0;
    out[O_PIX  + (n * 4 + 1) * HW + pix]  = px1;
    out[O_PIX  + (n * 4 + 2) * HW + pix]  = px2;
    out[O_PIX  + (n * 4 + 3) * HW + pix]  = px3;
    out[O_PRED + n * HW + pix]            = (float)lbl;
}

// Kernel 4: masked mean + exact top-k sum per (b,c).
__global__ __launch_bounds__(256) void reduce_topk_kernel(
    const float* __restrict__ mask, const float* __restrict__ pix)
{
    extern __shared__ unsigned skey[];
    __shared__ int   ibuf[256];
    __shared__ float fbuf[256];

    const int tid = threadIdx.x;
    const int b = blockIdx.x >> 2;
    const int c = blockIdx.x & 3;
    const float* pv = pix  + ((size_t)b * 4 + c) * HW;
    const float* mk = mask + (size_t)b * HW;

    for (int i = tid; i < HW; i += 256)
        skey[i] = (mk[i] > 0.5f) ? __float_as_uint(pv[i]) : 0u;
    __syncthreads();

    int   mc = 0;
    float ms = 0.f;
    for (int i = tid; i < HW; i += 256) {
        unsigned kk = skey[i];
        if (kk) { mc++; ms += __uint_as_float(kk); }
    }
    ibuf[tid] = mc; fbuf[tid] = ms;
    __syncthreads();
    for (int off = 128; off > 0; off >>= 1) {
        if (tid < off) { ibuf[tid] += ibuf[tid + off]; fbuf[tid] += fbuf[tid + off]; }
        __syncthreads();
    }
    const int   cnt    = ibuf[0];
    const float sumall = fbuf[0];
    __syncthreads();

    int k = (int)rintf((float)cnt * 0.2f);
    if (k < 1) k = 1;
    const int cmax = (cnt > 1) ? cnt : 1;
    if (k > cmax) k = cmax;

    unsigned prefix = 0u;
    for (int bit = 30; bit >= 0; bit--) {
        const unsigned cand = prefix | (1u << bit);
        int cl = 0;
        for (int i = tid; i < HW; i += 256)
            if (skey[i] >= cand) cl++;
        ibuf[tid] = cl;
        __syncthreads();
        for (int off = 128; off > 0; off >>= 1) {
            if (tid < off) ibuf[tid] += ibuf[tid + off];
            __syncthreads();
        }
        if (ibuf[0] >= k) prefix = cand;
        __syncthreads();
    }

    int   cg = 0;
    float sg = 0.f;
    for (int i = tid; i < HW; i += 256) {
        unsigned kk = skey[i];
        if (kk > prefix) { cg++; sg += __uint_as_float(kk); }
    }
    ibuf[tid] = cg; fbuf[tid] = sg;
    __syncthreads();
    for (int off = 128; off > 0; off >>= 1) {
        if (tid < off) { ibuf[tid] += ibuf[tid + off]; fbuf[tid] += fbuf[tid + off]; }
        __syncthreads();
    }
    if (tid == 0) {
        const float T = __uint_as_float(prefix);
        const float topsum = fbuf[0] + (float)(k - ibuf[0]) * T;
        g_mean_raw[b * 4 + c] = sumall / (float)((cnt > 1) ? cnt : 1);
        g_topk_raw[b * 4 + c] = topsum / (float)k;
        g_cnt[b] = cnt;
    }
}

// Kernel 5: finalize
__global__ void finalize_kernel(float* __restrict__ out)
{
    const int b = threadIdx.x;
    if (b >= BATCH) return;
    const int cnt = g_cnt[b];

    float m[4], t[4], a[4];
    float sm = 0.f, st = 0.f;
    for (int c = 0; c < 4; c++) {
        m[c] = (cnt == 0) ? 0.25f : fmaxf(g_mean_raw[b * 4 + c], 1e-8f);
        t[c] = (cnt == 0) ? 0.25f : fmaxf(g_topk_raw[b * 4 + c], 1e-8f);
        sm += m[c]; st += t[c];
    }
    sm = fmaxf(sm, 1e-8f); st = fmaxf(st, 1e-8f);
    float sa = 0.f;
    for (int c = 0; c < 4; c++) {
        m[c] /= sm; t[c] /= st;
        a[c] = fmaxf(0.7f * m[c] + 0.3f * t[c], 1e-8f);
        sa += a[c];
    }
    sa = fmaxf(sa, 1e-8f);
    int best = 0; float bv = -1.f;
    for (int c = 0; c < 4; c++) {
        a[c] /= sa;
        if (a[c] > bv) { bv = a[c]; best = c; }
        out[O_MEAN + b * 4 + c] = m[c];
        out[O_TOPK + b * 4 + c] = t[c];
        out[O_AGG  + b * 4 + c] = a[c];
    }
    out[O_AGGL + b] = (float)best;
}

extern "C" void kernel_launch(void* const* d_in, const int* in_sizes, int n_in,
                              void* d_out, int out_size)
{
    const float* fm   = (const float*)d_in[0];
    const float* mask = (const float*)d_in[1];
    const float* dw1  = (const float*)d_in[2];
    const float* dgs  = (const float*)d_in[3];
    const float* dgb  = (const float*)d_in[4];
    const float* dw2  = (const float*)d_in[5];
    const float* db2  = (const float*)d_in[6];
    const float* sw1  = (const float*)d_in[7];
    const float* sgs  = (const float*)d_in[8];
    const float* sgb  = (const float*)d_in[9];
    const float* sw2  = (const float*)d_in[10];
    const float* sb2  = (const float*)d_in[11];
    float* out = (float*)d_out;

    cudaFuncSetAttribute(conv_wino_kernel,
                         cudaFuncAttributeMaxDynamicSharedMemorySize, 2 * STAGE_BYTES);
    cudaFuncSetAttribute(reduce_topk_kernel,
                         cudaFuncAttributeMaxDynamicSharedMemorySize, HW * 4);

    convert_w_kernel<<<dim3(32, 18, 2), 256>>>(dw1, sw1);
    convert_in_kernel<<<dim3(4, 128, 8), 256>>>(fm);
    conv_wino_kernel<<<dim3(4, 512), 256, 2 * STAGE_BYTES>>>();
    gn_partA_kernel<<<2048, 256>>>();
    gn_partB_kernel<<<1, 128>>>();
    epilogue_kernel<<<NPIX / 256, 256>>>(dgs, dgb, dw2, db2, sgs, sgb, sw2, sb2, out);
    reduce_topk_kernel<<<BATCH * 4, 256, HW * 4>>>(mask, out + O_PIX);
    finalize_kernel<<<1, 32>>>(out);
}